// round 6
// baseline (speedup 1.0000x reference)
#include <cuda_runtime.h>
#include <math.h>

#define SS (512*512)
#define AD (60*729)

typedef unsigned long long u64t;

__device__ __forceinline__ u64t pk2(float lo, float hi) {
    u64t r;
    asm("mov.b64 %0, {%1, %2};" : "=l"(r) : "r"(__float_as_uint(lo)), "r"(__float_as_uint(hi)));
    return r;
}
__device__ __forceinline__ void fma2(u64t& d, u64t a, u64t b) {
    asm("fma.rn.f32x2 %0, %1, %2, %0;" : "+l"(d) : "l"(a), "l"(b));
}
__device__ __forceinline__ void upk2(u64t v, float& lo, float& hi) {
    unsigned int a, b;
    asm("mov.b64 {%0, %1}, %2;" : "=r"(a), "=r"(b) : "l"(v));
    lo = __uint_as_float(a); hi = __uint_as_float(b);
}

// ---------------- persistent device state ----------------
__device__ float g_fbuf[6*SS];    // ch0-4: f, ch5: backprojection
__device__ float g_hbuf[7*AD];    // ch0-4: h, ch5: Op_f, ch6: g (copied once)
__device__ float g_t1[32*SS];
__device__ float g_t2[32*SS];
__device__ float g_h1[AD];
__device__ float g_K2[1457];      // unwrapped ramp impulse response (scaled)

// ---------------- ramp filter impulse response ----------------
__global__ void k_ramp() {
    int o = blockIdx.x*blockDim.x + threadIdx.x;
    if (o >= 1457) return;
    int i = o - 728;
    int m = (i + 2048) & 2047;
    double kv;
    if (m == 0) {
        kv = 0.5;
    } else {
        const double PI = 3.14159265358979323846;
        double th = 2.0*PI*(double)m/2048.0;
        double c1 = cos(th), s1 = sin(th);
        double Nt = 1023.0*th;
        double cN = cos(Nt), sN = sin(Nt);
        double cN1 = cN*c1 - sN*s1, sN1 = sN*c1 + cN*s1;   // z^(N+1)
        double wr = 1.0 - 1024.0*cN + 1023.0*cN1;
        double wi =     - 1024.0*sN + 1023.0*sN1;
        double nr = c1*wr - s1*wi, ni = c1*wi + s1*wr;     // z*w
        double dr = 1.0 - c1, di = -s1;
        double d2r = dr*dr - di*di, d2i = 2.0*dr*di;       // (1-z)^2
        double dd = d2r*d2r + d2i*d2i;
        double Sre = (nr*d2r + ni*d2i)/dd;
        double f = 2.0*Sre + ((m & 1) ? -1024.0 : 1024.0);
        kv = (2.0/(2048.0*2048.0))*f;
    }
    g_K2[o] = (float)(kv * (3.14159265358979323846/120.0));
}

// ---------------- init ----------------
__global__ void k_init(const float* __restrict__ g) {
    int i = blockIdx.x*blockDim.x + threadIdx.x;
    int stride = gridDim.x*blockDim.x;
    for (int idx = i; idx < 5*SS; idx += stride) g_fbuf[idx] = 0.f;
    for (int idx = i; idx < 5*AD; idx += stride) g_hbuf[idx] = 0.f;
    for (int idx = i; idx < AD;   idx += stride) g_hbuf[6*AD+idx] = g[idx];
}

// ---------------- Radon forward: f ch1 -> g_hbuf ch5 ----------------
__global__ void k_radon_fwd(const float* __restrict__ theta) {
    __shared__ float red[4][64];
    int a = blockIdx.y;
    int tx = threadIdx.x, ty = threadIdx.y;
    int d = blockIdx.x*64 + tx;
    float ang = __ldg(theta + a);
    float ca = cosf(ang), sa = sinf(ang);
    const float* img = g_fbuf + SS;   // channel 1 of f
    float acc = 0.f;
    if (d < 729) {
        float s = (float)d - 364.0f;
        float bx = fmaf(s, ca, 255.5f);
        float by = fmaf(s, sa, 255.5f);
        int t0 = ty*128;
        for (int it = 0; it < 128; ++it) {
            float t = (float)(t0+it) - 255.5f;
            float px = fmaf(-t, sa, bx);
            float py = fmaf( t, ca, by);
            float xf = floorf(px), yf = floorf(py);
            int xi = (int)xf, yi = (int)yf;
            float fx = px - xf, fy = py - yf;
            if ((unsigned)xi < 511u && (unsigned)yi < 511u) {
                const float* p = img + yi*512 + xi;
                float v00 = __ldg(p), v01 = __ldg(p+1);
                float v10 = __ldg(p+512), v11 = __ldg(p+513);
                float top = fmaf(fx, v01 - v00, v00);
                float bot = fmaf(fx, v11 - v10, v10);
                acc += fmaf(fy, bot - top, top);
            } else if (xi >= -1 && xi <= 511 && yi >= -1 && yi <= 511) {
                bool x0v = (xi >= 0) && (xi < 512);
                bool x1v = (xi + 1) < 512;
                bool y0v = (yi >= 0) && (yi < 512);
                bool y1v = (yi + 1) < 512;
                const float* p = img + yi*512 + xi;
                float v00 = (x0v && y0v) ? __ldg(p)     : 0.f;
                float v01 = (x1v && y0v) ? __ldg(p+1)   : 0.f;
                float v10 = (x0v && y1v) ? __ldg(p+512) : 0.f;
                float v11 = (x1v && y1v) ? __ldg(p+513) : 0.f;
                float top = fmaf(fx, v01 - v00, v00);
                float bot = fmaf(fx, v11 - v10, v10);
                acc += fmaf(fy, bot - top, top);
            }
        }
    }
    red[ty][tx] = acc;
    __syncthreads();
    if (ty == 0 && d < 729)
        g_hbuf[5*AD + a*729 + d] = red[0][tx] + red[1][tx] + red[2][tx] + red[3][tx];
}

// ---------------- fused Ram-Lak filter: h ch0 -> g_h1 ----------------
// one block per angle; out[j] = sum_m row[m]*K2[j-m+728]
// sk padded to 1536 (max read index 728+255+512=1495); pad reads hit zeros
// and only affect lanes whose stores are guarded out.
__global__ void __launch_bounds__(256) k_filt() {
    __shared__ float srow[736];
    __shared__ float sk[1536];
    int a = blockIdx.x;
    int t = threadIdx.x;
    for (int i = t; i < 729; i += 256) srow[i] = g_hbuf[a*729 + i];
    for (int i = t; i < 1536; i += 256) sk[i] = (i < 1457) ? g_K2[i] : 0.f;
    __syncthreads();
    float a0 = 0.f, a1 = 0.f, a2 = 0.f;
    #pragma unroll 4
    for (int m = 0; m < 729; ++m) {
        float r = srow[m];
        int base = 728 - m;
        a0 = fmaf(r, sk[base + t],       a0);
        a1 = fmaf(r, sk[base + t + 256], a1);
        a2 = fmaf(r, sk[base + t + 512], a2);
    }
    g_h1[a*729 + t] = a0;
    g_h1[a*729 + t + 256] = a1;
    if (t < 217) g_h1[a*729 + t + 512] = a2;
}

// ---------------- backprojection: g_h1 -> g_fbuf ch5 ----------------
__global__ void k_backproj(const float* __restrict__ theta) {
    __shared__ float sc[60], ssn[60];
    int tid = threadIdx.y*blockDim.x + threadIdx.x;
    if (tid < 60) { float a = theta[tid]; sc[tid] = cosf(a); ssn[tid] = sinf(a); }
    __syncthreads();
    int x = blockIdx.x*blockDim.x + threadIdx.x;
    int y = blockIdx.y*blockDim.y + threadIdx.y;
    float xo = (float)x - 255.5f, yo = (float)y - 255.5f;
    float acc = 0.f;
    #pragma unroll 4
    for (int a = 0; a < 60; ++a) {
        float sidx = fmaf(xo, sc[a], fmaf(yo, ssn[a], 364.0f));
        float sf = floorf(sidx);
        int si = (int)sf;
        float fr = sidx - sf;
        const float* row = g_h1 + a*729;
        float v0 = ((unsigned)si       < 729u) ? __ldg(row + si)     : 0.f;
        float v1 = ((unsigned)(si + 1) < 729u) ? __ldg(row + si + 1) : 0.f;
        acc += fmaf(fr, v1 - v0, v0);
    }
    g_fbuf[5*SS + y*512 + x] = acc;
}

// ---------------- 3x3 SAME conv v5: packed f32x2, 4 px/thread ----------------
template<int CIN, int OCH, int TH, bool PRELU, bool ADDTO>
__global__ void __launch_bounds__(16*TH) conv3x3_v5(
    const float* __restrict__ in, float* __restrict__ out,
    const float* __restrict__ w, const float* __restrict__ bias,
    const float* __restrict__ slope, int H, int W)
{
    constexpr int CH = 4;
    constexpr int TW = 64;
    constexpr int LW = 68;
    constexpr int BS = 16*TH;
    __shared__ float2 sW[OCH*CIN*9];
    __shared__ float sIn[CH*(TH+2)*LW];

    int tx = threadIdx.x, ty = threadIdx.y;
    int tid = ty*16 + tx;
    int bx = blockIdx.x*TW, by = blockIdx.y*TH;
    int zo = blockIdx.z*OCH;
    size_t HW = (size_t)H*W;

    for (int i = tid; i < OCH*CIN*9; i += BS) {
        float v = __ldg(w + zo*CIN*9 + i);
        sW[i] = make_float2(v, v);
    }

    float sl = PRELU ? __ldg(slope) : 0.f;
    u64t acc[OCH][2];
    #pragma unroll
    for (int o = 0; o < OCH; ++o) {
        float bb = __ldg(bias + zo + o);
        u64t bp = pk2(bb, bb);
        acc[o][0] = bp; acc[o][1] = bp;
    }

    constexpr int NCH = (CIN + CH - 1)/CH;
    #pragma unroll 1
    for (int chunk = 0; chunk < NCH; ++chunk) {
        int ic0 = chunk*CH;
        int cc = (CIN - ic0 < CH) ? (CIN - ic0) : CH;
        __syncthreads();
        int tot = cc*(TH+2)*66;
        for (int i = tid; i < tot; i += BS) {
            int c = i/((TH+2)*66);
            int rem = i - c*((TH+2)*66);
            int ly = rem/66, lx = rem - ly*66;
            int gy = by + ly - 1, gx = bx + lx - 1;
            float v = 0.f;
            if ((unsigned)gy < (unsigned)H && (unsigned)gx < (unsigned)W)
                v = __ldg(in + (size_t)(ic0 + c)*HW + (size_t)gy*W + gx);
            sIn[(c*(TH+2) + ly)*LW + lx] = v;
        }
        __syncthreads();
        #pragma unroll
        for (int c = 0; c < CH; ++c) {
            if (c >= cc) break;
            u64t pr[3][5];
            #pragma unroll
            for (int ry = 0; ry < 3; ++ry) {
                const float* rp = &sIn[(c*(TH+2) + ty + ry)*LW + tx*4];
                float4 v4 = *reinterpret_cast<const float4*>(rp);
                float r4 = rp[4], r5 = rp[5];
                pr[ry][0] = pk2(v4.x, v4.y);
                pr[ry][1] = pk2(v4.y, v4.z);
                pr[ry][2] = pk2(v4.z, v4.w);
                pr[ry][3] = pk2(v4.w, r4);
                pr[ry][4] = pk2(r4, r5);
            }
            const float2* wb = &sW[(ic0 + c)*9];
            #pragma unroll
            for (int o = 0; o < OCH; ++o) {
                const u64t* wo = reinterpret_cast<const u64t*>(wb + o*CIN*9);
                #pragma unroll
                for (int ky = 0; ky < 3; ++ky)
                    #pragma unroll
                    for (int kx = 0; kx < 3; ++kx) {
                        u64t wv = wo[ky*3 + kx];
                        fma2(acc[o][0], wv, pr[ky][kx]);
                        fma2(acc[o][1], wv, pr[ky][kx + 2]);
                    }
            }
        }
    }

    int y = by + ty;
    int x0 = bx + tx*4;
    if (y < H) {
        bool fullvec = ((W & 3) == 0) && (x0 + 4 <= W);
        #pragma unroll
        for (int o = 0; o < OCH; ++o) {
            float* op = out + (size_t)(zo + o)*HW + (size_t)y*W;
            float v[4];
            upk2(acc[o][0], v[0], v[1]);
            upk2(acc[o][1], v[2], v[3]);
            if (PRELU) {
                #pragma unroll
                for (int p = 0; p < 4; ++p) v[p] = (v[p] >= 0.f) ? v[p] : sl*v[p];
            }
            if (fullvec) {
                float4* dst = reinterpret_cast<float4*>(op + x0);
                if (ADDTO) {
                    float4 e = dst[0];
                    e.x += v[0]; e.y += v[1]; e.z += v[2]; e.w += v[3];
                    dst[0] = e;
                } else {
                    dst[0] = make_float4(v[0], v[1], v[2], v[3]);
                }
            } else {
                #pragma unroll
                for (int p = 0; p < 4; ++p) {
                    int x = x0 + p;
                    if (x < W) {
                        if (ADDTO) op[x] += v[p];
                        else       op[x] = v[p];
                    }
                }
            }
        }
    }
}

// ---------------- output writer ----------------
__global__ void k_out(float* __restrict__ out, int n) {
    int i = blockIdx.x*blockDim.x + threadIdx.x;
    if (i < n) out[i] = g_fbuf[i % SS];
}

// ---------------- launch ----------------
extern "C" void kernel_launch(void* const* d_in, const int* in_sizes, int n_in,
                              void* d_out, int out_size) {
    (void)in_sizes; (void)n_in;
    const float* g     = (const float*)d_in[2];
    const float* theta = (const float*)d_in[3];
    const float* dw1 = (const float*)d_in[5];
    const float* db1 = (const float*)d_in[6];
    const float* da1 = (const float*)d_in[7];
    const float* dw2 = (const float*)d_in[8];
    const float* db2 = (const float*)d_in[9];
    const float* da2 = (const float*)d_in[10];
    const float* dw3 = (const float*)d_in[11];
    const float* db3 = (const float*)d_in[12];
    const float* pw1 = (const float*)d_in[13];
    const float* pb1 = (const float*)d_in[14];
    const float* pa1 = (const float*)d_in[15];
    const float* pw2 = (const float*)d_in[16];
    const float* pb2 = (const float*)d_in[17];
    const float* pa2 = (const float*)d_in[18];
    const float* pw3 = (const float*)d_in[19];
    const float* pb3 = (const float*)d_in[20];

    float *fbuf, *hbuf, *t1, *t2;
    cudaGetSymbolAddress((void**)&fbuf, g_fbuf);
    cudaGetSymbolAddress((void**)&hbuf, g_hbuf);
    cudaGetSymbolAddress((void**)&t1, g_t1);
    cudaGetSymbolAddress((void**)&t2, g_t2);

    k_ramp<<<6, 256>>>();
    k_init<<<512, 256>>>(g);

    // dual: W=729 -> 12 x-tiles of 64; H=60 -> 8 y-tiles of 8
    dim3 gD1(12, 8, 4), bD(16, 8);     // OCH=8, TH=8
    dim3 gD2(12, 8, 4);
    dim3 gD3(12, 15, 1), bD3(16, 4);   // OCH=5, TH=4
    // primal: 512x512, TH=8 -> y=64
    dim3 gP1(8, 64, 4), bP(16, 8);     // OCH=8, TH=8, 2048 blocks
    dim3 gP2(8, 64, 4);
    dim3 gP3(8, 64, 1);

    for (int i = 0; i < 10; ++i) {
        // dual step
        k_radon_fwd<<<dim3(12, 60), dim3(64, 4)>>>(theta);
        conv3x3_v5<7, 8, 8, true, false><<<gD1, bD>>>(hbuf, t1, dw1 + i*32*7*9, db1 + i*32, da1 + i, 60, 729);
        conv3x3_v5<32, 8, 8, true, false><<<gD2, bD>>>(t1, t2, dw2 + i*32*32*9, db2 + i*32, da2 + i, 60, 729);
        conv3x3_v5<32, 5, 4, false, true><<<gD3, bD3>>>(t2, hbuf, dw3 + i*5*32*9, db3 + i*5, (const float*)0, 60, 729);
        // filter + backprojection
        k_filt<<<60, 256>>>();
        k_backproj<<<dim3(16, 64), dim3(32, 8)>>>(theta);
        // primal step
        conv3x3_v5<6, 8, 8, true, false><<<gP1, bP>>>(fbuf, t1, pw1 + i*32*6*9, pb1 + i*32, pa1 + i, 512, 512);
        conv3x3_v5<32, 8, 8, true, false><<<gP2, bP>>>(t1, t2, pw2 + i*32*32*9, pb2 + i*32, pa2 + i, 512, 512);
        conv3x3_v5<32, 5, 8, false, true><<<gP3, bP>>>(t2, fbuf, pw3 + i*5*32*9, pb3 + i*5, (const float*)0, 512, 512);
    }

    k_out<<<(out_size + 255)/256, 256>>>((float*)d_out, out_size);
}

// round 7
// speedup vs baseline: 1.1071x; 1.1071x over previous
#include <cuda_runtime.h>
#include <math.h>

#define SS (512*512)
#define AD (60*729)

// ---------------- persistent device state ----------------
__device__ float g_fbuf[6*SS];    // ch0-4: f, ch5: backprojection
__device__ float g_hbuf[7*AD];    // ch0-4: h, ch5: Op_f, ch6: g (copied once)
__device__ float g_t1[32*SS];
__device__ float g_t2[32*SS];
__device__ float g_h1[AD];
__device__ float g_K2[1457];      // unwrapped ramp impulse response (scaled)

// ---------------- ramp filter impulse response ----------------
__global__ void k_ramp() {
    int o = blockIdx.x*blockDim.x + threadIdx.x;
    if (o >= 1457) return;
    int i = o - 728;
    int m = (i + 2048) & 2047;
    double kv;
    if (m == 0) {
        kv = 0.5;
    } else {
        const double PI = 3.14159265358979323846;
        double th = 2.0*PI*(double)m/2048.0;
        double c1 = cos(th), s1 = sin(th);
        double Nt = 1023.0*th;
        double cN = cos(Nt), sN = sin(Nt);
        double cN1 = cN*c1 - sN*s1, sN1 = sN*c1 + cN*s1;   // z^(N+1)
        double wr = 1.0 - 1024.0*cN + 1023.0*cN1;
        double wi =     - 1024.0*sN + 1023.0*sN1;
        double nr = c1*wr - s1*wi, ni = c1*wi + s1*wr;     // z*w
        double dr = 1.0 - c1, di = -s1;
        double d2r = dr*dr - di*di, d2i = 2.0*dr*di;       // (1-z)^2
        double dd = d2r*d2r + d2i*d2i;
        double Sre = (nr*d2r + ni*d2i)/dd;
        double f = 2.0*Sre + ((m & 1) ? -1024.0 : 1024.0);
        kv = (2.0/(2048.0*2048.0))*f;
    }
    g_K2[o] = (float)(kv * (3.14159265358979323846/120.0));
}

// ---------------- init ----------------
__global__ void k_init(const float* __restrict__ g) {
    int i = blockIdx.x*blockDim.x + threadIdx.x;
    int stride = gridDim.x*blockDim.x;
    for (int idx = i; idx < 5*SS; idx += stride) g_fbuf[idx] = 0.f;
    for (int idx = i; idx < 5*AD; idx += stride) g_hbuf[idx] = 0.f;
    for (int idx = i; idx < AD;   idx += stride) g_hbuf[6*AD+idx] = g[idx];
}

// ---------------- Radon forward: f ch1 -> g_hbuf ch5 ----------------
// with analytic valid-t-range clamping; body numerics identical to reference.
__global__ void k_radon_fwd(const float* __restrict__ theta) {
    __shared__ float red[4][64];
    int a = blockIdx.y;
    int tx = threadIdx.x, ty = threadIdx.y;
    int d = blockIdx.x*64 + tx;
    float ang = __ldg(theta + a);
    float ca = cosf(ang), sa = sinf(ang);
    const float* img = g_fbuf + SS;   // channel 1 of f
    float acc = 0.f;
    if (d < 729) {
        float s = (float)d - 364.0f;
        float bx = fmaf(s, ca, 255.5f);
        float by = fmaf(s, sa, 255.5f);
        // valid t range (t = it - 255.5): px = bx - t*sa in (-1,512), py = by + t*ca in (-1,512)
        float t_lo = -1e9f, t_hi = 1e9f;
        if (sa > 1e-6f) {
            t_lo = fmaxf(t_lo, (bx - 512.0f)/sa);
            t_hi = fminf(t_hi, (bx + 1.0f)/sa);
        } else if (bx <= -1.0f || bx >= 512.0f) {
            t_hi = -2e9f;
        }
        if (ca > 1e-6f) {
            t_lo = fmaxf(t_lo, (-1.0f - by)/ca);
            t_hi = fminf(t_hi, (512.0f - by)/ca);
        } else if (ca < -1e-6f) {
            t_lo = fmaxf(t_lo, (512.0f - by)/ca);
            t_hi = fminf(t_hi, (-1.0f - by)/ca);
        } else if (by <= -1.0f || by >= 512.0f) {
            t_hi = -2e9f;
        }
        int t0 = ty*128;
        int lo = t0, hi = t0 + 128;
        float fl = floorf(t_lo + 255.5f) - 1.0f;
        float fh = ceilf (t_hi + 255.5f) + 2.0f;
        fl = fmaxf(fl, (float)lo); fh = fminf(fh, (float)hi);
        if (fl > (float)lo) lo = (int)fl;
        if (fh < (float)hi) hi = (fh < (float)t0) ? t0 : (int)fh;
        for (int it = lo; it < hi; ++it) {
            float t = (float)it - 255.5f;
            float px = fmaf(-t, sa, bx);
            float py = fmaf( t, ca, by);
            float xf = floorf(px), yf = floorf(py);
            int xi = (int)xf, yi = (int)yf;
            float fx = px - xf, fy = py - yf;
            if ((unsigned)xi < 511u && (unsigned)yi < 511u) {
                const float* p = img + yi*512 + xi;
                float v00 = __ldg(p), v01 = __ldg(p+1);
                float v10 = __ldg(p+512), v11 = __ldg(p+513);
                float top = fmaf(fx, v01 - v00, v00);
                float bot = fmaf(fx, v11 - v10, v10);
                acc += fmaf(fy, bot - top, top);
            } else if (xi >= -1 && xi <= 511 && yi >= -1 && yi <= 511) {
                bool x0v = (xi >= 0) && (xi < 512);
                bool x1v = (xi + 1) < 512;
                bool y0v = (yi >= 0) && (yi < 512);
                bool y1v = (yi + 1) < 512;
                const float* p = img + yi*512 + xi;
                float v00 = (x0v && y0v) ? __ldg(p)     : 0.f;
                float v01 = (x1v && y0v) ? __ldg(p+1)   : 0.f;
                float v10 = (x0v && y1v) ? __ldg(p+512) : 0.f;
                float v11 = (x1v && y1v) ? __ldg(p+513) : 0.f;
                float top = fmaf(fx, v01 - v00, v00);
                float bot = fmaf(fx, v11 - v10, v10);
                acc += fmaf(fy, bot - top, top);
            }
        }
    }
    red[ty][tx] = acc;
    __syncthreads();
    if (ty == 0 && d < 729)
        g_hbuf[5*AD + a*729 + d] = red[0][tx] + red[1][tx] + red[2][tx] + red[3][tx];
}

// ---------------- fused Ram-Lak filter: h ch0 -> g_h1 ----------------
// sk padded to 1536 (max read index 1495); pad reads hit zeros and only
// affect lanes whose stores are guarded out.
__global__ void __launch_bounds__(256) k_filt() {
    __shared__ float srow[736];
    __shared__ float sk[1536];
    int a = blockIdx.x;
    int t = threadIdx.x;
    for (int i = t; i < 729; i += 256) srow[i] = g_hbuf[a*729 + i];
    for (int i = t; i < 1536; i += 256) sk[i] = (i < 1457) ? g_K2[i] : 0.f;
    __syncthreads();
    float a0 = 0.f, a1 = 0.f, a2 = 0.f;
    #pragma unroll 4
    for (int m = 0; m < 729; ++m) {
        float r = srow[m];
        int base = 728 - m;
        a0 = fmaf(r, sk[base + t],       a0);
        a1 = fmaf(r, sk[base + t + 256], a1);
        a2 = fmaf(r, sk[base + t + 512], a2);
    }
    g_h1[a*729 + t] = a0;
    g_h1[a*729 + t + 256] = a1;
    if (t < 217) g_h1[a*729 + t + 512] = a2;
}

// ---------------- backprojection v2: smem detector windows ----------------
// block 32x16 pixels; per angle the needed detector window is <= 36 wide.
// Stage 60 x 64 floats (zeros outside [0,729), matching cval=0), lerp from LDS.
__global__ void __launch_bounds__(512) k_backproj(const float* __restrict__ theta) {
    __shared__ float sc[60], ssn[60];
    __shared__ int   smin[60];
    __shared__ float srow[60*64];
    int tx = threadIdx.x, ty = threadIdx.y;
    int tid = ty*32 + tx;
    int bx = blockIdx.x*32, by = blockIdx.y*16;
    float x0 = (float)bx - 255.5f, x1 = x0 + 31.0f;
    float y0 = (float)by - 255.5f, y1 = y0 + 15.0f;
    if (tid < 60) {
        float ang = __ldg(theta + tid);
        float ca = cosf(ang), sa = sinf(ang);
        sc[tid] = ca; ssn[tid] = sa;
        float mx = fminf(x0*ca, x1*ca) + fminf(y0*sa, y1*sa) + 364.0f;
        smin[tid] = (int)floorf(mx);
    }
    __syncthreads();
    for (int i = tid; i < 60*64; i += 512) {
        int a = i >> 6, off = i & 63;
        int idx = smin[a] + off;
        srow[i] = ((unsigned)idx < 729u) ? __ldg(g_h1 + a*729 + idx) : 0.f;
    }
    __syncthreads();
    int x = bx + tx, y = by + ty;
    float xo = (float)x - 255.5f, yo = (float)y - 255.5f;
    float acc = 0.f;
    #pragma unroll 4
    for (int a = 0; a < 60; ++a) {
        float sidx = fmaf(xo, sc[a], fmaf(yo, ssn[a], 364.0f));
        float sf = floorf(sidx);
        float fr = sidx - sf;
        int local = (int)sf - smin[a];
        const float* rp = &srow[a*64 + local];
        float v0 = rp[0], v1 = rp[1];
        acc += fmaf(fr, v1 - v0, v0);
    }
    g_fbuf[5*SS + y*512 + x] = acc;
}

// ---------------- 3x3 SAME conv v4 (round-4 winner) ----------------
template<int CIN, int OCH, int TH, bool PRELU, bool ADDTO>
__global__ void __launch_bounds__(16*TH) conv3x3_v4(
    const float* __restrict__ in, float* __restrict__ out,
    const float* __restrict__ w, const float* __restrict__ bias,
    const float* __restrict__ slope, int H, int W)
{
    constexpr int CH = 4;
    constexpr int TW = 64;
    constexpr int LW = 68;
    constexpr int BS = 16*TH;
    __shared__ float sW[OCH*CIN*9];
    __shared__ float sIn[CH*(TH+2)*LW];

    int tx = threadIdx.x, ty = threadIdx.y;
    int tid = ty*16 + tx;
    int bx = blockIdx.x*TW, by = blockIdx.y*TH;
    int zo = blockIdx.z*OCH;
    size_t HW = (size_t)H*W;

    for (int i = tid; i < OCH*CIN*9; i += BS) sW[i] = __ldg(w + zo*CIN*9 + i);

    float sl = PRELU ? __ldg(slope) : 0.f;
    float acc[OCH][4];
    #pragma unroll
    for (int o = 0; o < OCH; ++o) {
        float bb = __ldg(bias + zo + o);
        #pragma unroll
        for (int p = 0; p < 4; ++p) acc[o][p] = bb;
    }

    constexpr int NCH = (CIN + CH - 1)/CH;
    #pragma unroll 1
    for (int chunk = 0; chunk < NCH; ++chunk) {
        int ic0 = chunk*CH;
        int cc = (CIN - ic0 < CH) ? (CIN - ic0) : CH;
        __syncthreads();
        int tot = cc*(TH+2)*66;
        for (int i = tid; i < tot; i += BS) {
            int c = i/((TH+2)*66);
            int rem = i - c*((TH+2)*66);
            int ly = rem/66, lx = rem - ly*66;
            int gy = by + ly - 1, gx = bx + lx - 1;
            float v = 0.f;
            if ((unsigned)gy < (unsigned)H && (unsigned)gx < (unsigned)W)
                v = __ldg(in + (size_t)(ic0 + c)*HW + (size_t)gy*W + gx);
            sIn[(c*(TH+2) + ly)*LW + lx] = v;
        }
        __syncthreads();
        #pragma unroll
        for (int c = 0; c < CH; ++c) {
            if (c >= cc) break;
            float r[3][6];
            #pragma unroll
            for (int ry = 0; ry < 3; ++ry) {
                const float* rp = &sIn[(c*(TH+2) + ty + ry)*LW + tx*4];
                float4 v4 = *reinterpret_cast<const float4*>(rp);
                r[ry][0] = v4.x; r[ry][1] = v4.y; r[ry][2] = v4.z; r[ry][3] = v4.w;
                r[ry][4] = rp[4]; r[ry][5] = rp[5];
            }
            const float* wb = &sW[(ic0 + c)*9];
            #pragma unroll
            for (int o = 0; o < OCH; ++o) {
                const float* wo = wb + o*CIN*9;
                #pragma unroll
                for (int ky = 0; ky < 3; ++ky)
                    #pragma unroll
                    for (int kx = 0; kx < 3; ++kx) {
                        float wv = wo[ky*3 + kx];
                        #pragma unroll
                        for (int p = 0; p < 4; ++p)
                            acc[o][p] = fmaf(wv, r[ky][kx+p], acc[o][p]);
                    }
            }
        }
    }

    int y = by + ty;
    int x0 = bx + tx*4;
    if (y < H) {
        bool fullvec = ((W & 3) == 0) && (x0 + 4 <= W);
        #pragma unroll
        for (int o = 0; o < OCH; ++o) {
            float* op = out + (size_t)(zo + o)*HW + (size_t)y*W;
            float v[4];
            #pragma unroll
            for (int p = 0; p < 4; ++p) {
                v[p] = acc[o][p];
                if (PRELU) v[p] = (v[p] >= 0.f) ? v[p] : sl*v[p];
            }
            if (fullvec) {
                float4* dst = reinterpret_cast<float4*>(op + x0);
                if (ADDTO) {
                    float4 e = dst[0];
                    e.x += v[0]; e.y += v[1]; e.z += v[2]; e.w += v[3];
                    dst[0] = e;
                } else {
                    dst[0] = make_float4(v[0], v[1], v[2], v[3]);
                }
            } else {
                #pragma unroll
                for (int p = 0; p < 4; ++p) {
                    int x = x0 + p;
                    if (x < W) {
                        if (ADDTO) op[x] += v[p];
                        else       op[x] = v[p];
                    }
                }
            }
        }
    }
}

// ---------------- output writer ----------------
__global__ void k_out(float* __restrict__ out, int n) {
    int i = blockIdx.x*blockDim.x + threadIdx.x;
    if (i < n) out[i] = g_fbuf[i % SS];
}

// ---------------- launch ----------------
extern "C" void kernel_launch(void* const* d_in, const int* in_sizes, int n_in,
                              void* d_out, int out_size) {
    (void)in_sizes; (void)n_in;
    const float* g     = (const float*)d_in[2];
    const float* theta = (const float*)d_in[3];
    const float* dw1 = (const float*)d_in[5];
    const float* db1 = (const float*)d_in[6];
    const float* da1 = (const float*)d_in[7];
    const float* dw2 = (const float*)d_in[8];
    const float* db2 = (const float*)d_in[9];
    const float* da2 = (const float*)d_in[10];
    const float* dw3 = (const float*)d_in[11];
    const float* db3 = (const float*)d_in[12];
    const float* pw1 = (const float*)d_in[13];
    const float* pb1 = (const float*)d_in[14];
    const float* pa1 = (const float*)d_in[15];
    const float* pw2 = (const float*)d_in[16];
    const float* pb2 = (const float*)d_in[17];
    const float* pa2 = (const float*)d_in[18];
    const float* pw3 = (const float*)d_in[19];
    const float* pb3 = (const float*)d_in[20];

    float *fbuf, *hbuf, *t1, *t2;
    cudaGetSymbolAddress((void**)&fbuf, g_fbuf);
    cudaGetSymbolAddress((void**)&hbuf, g_hbuf);
    cudaGetSymbolAddress((void**)&t1, g_t1);
    cudaGetSymbolAddress((void**)&t2, g_t2);

    k_ramp<<<6, 256>>>();
    k_init<<<512, 256>>>(g);

    // dual: W=729 -> 12 x-tiles of 64; H=60 -> 8 y-tiles of 8
    dim3 gD1(12, 8, 4), bD1(16, 8);
    dim3 gD2(12, 8, 4), bD2(16, 8);
    dim3 gD3(12, 15, 1), bD3(16, 4);
    // primal: 512x512
    dim3 gP1(8, 32, 4), bP1(16, 16);
    dim3 gP2(8, 32, 4), bP2(16, 16);
    dim3 gP3(8, 64, 1), bP3(16, 8);

    for (int i = 0; i < 10; ++i) {
        // dual step
        k_radon_fwd<<<dim3(12, 60), dim3(64, 4)>>>(theta);
        conv3x3_v4<7, 8, 8, true, false><<<gD1, bD1>>>(hbuf, t1, dw1 + i*32*7*9, db1 + i*32, da1 + i, 60, 729);
        conv3x3_v4<32, 8, 8, true, false><<<gD2, bD2>>>(t1, t2, dw2 + i*32*32*9, db2 + i*32, da2 + i, 60, 729);
        conv3x3_v4<32, 5, 4, false, true><<<gD3, bD3>>>(t2, hbuf, dw3 + i*5*32*9, db3 + i*5, (const float*)0, 60, 729);
        // filter + backprojection
        k_filt<<<60, 256>>>();
        k_backproj<<<dim3(16, 32), dim3(32, 16)>>>(theta);
        // primal step
        conv3x3_v4<6, 8, 16, true, false><<<gP1, bP1>>>(fbuf, t1, pw1 + i*32*6*9, pb1 + i*32, pa1 + i, 512, 512);
        conv3x3_v4<32, 8, 16, true, false><<<gP2, bP2>>>(t1, t2, pw2 + i*32*32*9, pb2 + i*32, pa2 + i, 512, 512);
        conv3x3_v4<32, 5, 8, false, true><<<gP3, bP3>>>(t2, fbuf, pw3 + i*5*32*9, pb3 + i*5, (const float*)0, 512, 512);
    }

    k_out<<<(out_size + 255)/256, 256>>>((float*)d_out, out_size);
}

// round 8
// speedup vs baseline: 1.1081x; 1.0009x over previous
#include <cuda_runtime.h>
#include <math.h>

#define SS (512*512)
#define AD (60*729)

// ---------------- persistent device state ----------------
__device__ float g_fbuf[6*SS];    // ch0-4: f, ch5: backprojection
__device__ float g_hbuf[7*AD];    // ch0-4: h, ch5: Op_f, ch6: g (copied once)
__device__ float g_t1[32*SS];
__device__ float g_t2[32*SS];
__device__ float g_h1[AD];
__device__ float g_K2[1457];      // unwrapped ramp impulse response (scaled)

// ---------------- ramp filter impulse response ----------------
__global__ void k_ramp() {
    int o = blockIdx.x*blockDim.x + threadIdx.x;
    if (o >= 1457) return;
    int i = o - 728;
    int m = (i + 2048) & 2047;
    double kv;
    if (m == 0) {
        kv = 0.5;
    } else {
        const double PI = 3.14159265358979323846;
        double th = 2.0*PI*(double)m/2048.0;
        double c1 = cos(th), s1 = sin(th);
        double Nt = 1023.0*th;
        double cN = cos(Nt), sN = sin(Nt);
        double cN1 = cN*c1 - sN*s1, sN1 = sN*c1 + cN*s1;   // z^(N+1)
        double wr = 1.0 - 1024.0*cN + 1023.0*cN1;
        double wi =     - 1024.0*sN + 1023.0*sN1;
        double nr = c1*wr - s1*wi, ni = c1*wi + s1*wr;     // z*w
        double dr = 1.0 - c1, di = -s1;
        double d2r = dr*dr - di*di, d2i = 2.0*dr*di;       // (1-z)^2
        double dd = d2r*d2r + d2i*d2i;
        double Sre = (nr*d2r + ni*d2i)/dd;
        double f = 2.0*Sre + ((m & 1) ? -1024.0 : 1024.0);
        kv = (2.0/(2048.0*2048.0))*f;
    }
    g_K2[o] = (float)(kv * (3.14159265358979323846/120.0));
}

// ---------------- init ----------------
__global__ void k_init(const float* __restrict__ g) {
    int i = blockIdx.x*blockDim.x + threadIdx.x;
    int stride = gridDim.x*blockDim.x;
    for (int idx = i; idx < 5*SS; idx += stride) g_fbuf[idx] = 0.f;
    for (int idx = i; idx < 5*AD; idx += stride) g_hbuf[idx] = 0.f;
    for (int idx = i; idx < AD;   idx += stride) g_hbuf[6*AD+idx] = g[idx];
}

// ---------------- Radon forward: f ch1 -> g_hbuf ch5 ----------------
// with analytic valid-t-range clamping; body numerics identical to reference.
__global__ void k_radon_fwd(const float* __restrict__ theta) {
    __shared__ float red[4][64];
    int a = blockIdx.y;
    int tx = threadIdx.x, ty = threadIdx.y;
    int d = blockIdx.x*64 + tx;
    float ang = __ldg(theta + a);
    float ca = cosf(ang), sa = sinf(ang);
    const float* img = g_fbuf + SS;   // channel 1 of f
    float acc = 0.f;
    if (d < 729) {
        float s = (float)d - 364.0f;
        float bx = fmaf(s, ca, 255.5f);
        float by = fmaf(s, sa, 255.5f);
        float t_lo = -1e9f, t_hi = 1e9f;
        if (sa > 1e-6f) {
            t_lo = fmaxf(t_lo, (bx - 512.0f)/sa);
            t_hi = fminf(t_hi, (bx + 1.0f)/sa);
        } else if (bx <= -1.0f || bx >= 512.0f) {
            t_hi = -2e9f;
        }
        if (ca > 1e-6f) {
            t_lo = fmaxf(t_lo, (-1.0f - by)/ca);
            t_hi = fminf(t_hi, (512.0f - by)/ca);
        } else if (ca < -1e-6f) {
            t_lo = fmaxf(t_lo, (512.0f - by)/ca);
            t_hi = fminf(t_hi, (-1.0f - by)/ca);
        } else if (by <= -1.0f || by >= 512.0f) {
            t_hi = -2e9f;
        }
        int t0 = ty*128;
        int lo = t0, hi = t0 + 128;
        float fl = floorf(t_lo + 255.5f) - 1.0f;
        float fh = ceilf (t_hi + 255.5f) + 2.0f;
        fl = fmaxf(fl, (float)lo); fh = fminf(fh, (float)hi);
        if (fl > (float)lo) lo = (int)fl;
        if (fh < (float)hi) hi = (fh < (float)t0) ? t0 : (int)fh;
        for (int it = lo; it < hi; ++it) {
            float t = (float)it - 255.5f;
            float px = fmaf(-t, sa, bx);
            float py = fmaf( t, ca, by);
            float xf = floorf(px), yf = floorf(py);
            int xi = (int)xf, yi = (int)yf;
            float fx = px - xf, fy = py - yf;
            if ((unsigned)xi < 511u && (unsigned)yi < 511u) {
                const float* p = img + yi*512 + xi;
                float v00 = __ldg(p), v01 = __ldg(p+1);
                float v10 = __ldg(p+512), v11 = __ldg(p+513);
                float top = fmaf(fx, v01 - v00, v00);
                float bot = fmaf(fx, v11 - v10, v10);
                acc += fmaf(fy, bot - top, top);
            } else if (xi >= -1 && xi <= 511 && yi >= -1 && yi <= 511) {
                bool x0v = (xi >= 0) && (xi < 512);
                bool x1v = (xi + 1) < 512;
                bool y0v = (yi >= 0) && (yi < 512);
                bool y1v = (yi + 1) < 512;
                const float* p = img + yi*512 + xi;
                float v00 = (x0v && y0v) ? __ldg(p)     : 0.f;
                float v01 = (x1v && y0v) ? __ldg(p+1)   : 0.f;
                float v10 = (x0v && y1v) ? __ldg(p+512) : 0.f;
                float v11 = (x1v && y1v) ? __ldg(p+513) : 0.f;
                float top = fmaf(fx, v01 - v00, v00);
                float bot = fmaf(fx, v11 - v10, v10);
                acc += fmaf(fy, bot - top, top);
            }
        }
    }
    red[ty][tx] = acc;
    __syncthreads();
    if (ty == 0 && d < 729)
        g_hbuf[5*AD + a*729 + d] = red[0][tx] + red[1][tx] + red[2][tx] + red[3][tx];
}

// ---------------- fused Ram-Lak filter: h ch0 -> g_h1 ----------------
__global__ void __launch_bounds__(256) k_filt() {
    __shared__ float srow[736];
    __shared__ float sk[1536];
    int a = blockIdx.x;
    int t = threadIdx.x;
    for (int i = t; i < 729; i += 256) srow[i] = g_hbuf[a*729 + i];
    for (int i = t; i < 1536; i += 256) sk[i] = (i < 1457) ? g_K2[i] : 0.f;
    __syncthreads();
    float a0 = 0.f, a1 = 0.f, a2 = 0.f;
    #pragma unroll 4
    for (int m = 0; m < 729; ++m) {
        float r = srow[m];
        int base = 728 - m;
        a0 = fmaf(r, sk[base + t],       a0);
        a1 = fmaf(r, sk[base + t + 256], a1);
        a2 = fmaf(r, sk[base + t + 512], a2);
    }
    g_h1[a*729 + t] = a0;
    g_h1[a*729 + t + 256] = a1;
    if (t < 217) g_h1[a*729 + t + 512] = a2;
}

// ---------------- backprojection v2: smem detector windows ----------------
__global__ void __launch_bounds__(512) k_backproj(const float* __restrict__ theta) {
    __shared__ float sc[60], ssn[60];
    __shared__ int   smin[60];
    __shared__ float srow[60*64];
    int tx = threadIdx.x, ty = threadIdx.y;
    int tid = ty*32 + tx;
    int bx = blockIdx.x*32, by = blockIdx.y*16;
    float x0 = (float)bx - 255.5f, x1 = x0 + 31.0f;
    float y0 = (float)by - 255.5f, y1 = y0 + 15.0f;
    if (tid < 60) {
        float ang = __ldg(theta + tid);
        float ca = cosf(ang), sa = sinf(ang);
        sc[tid] = ca; ssn[tid] = sa;
        float mx = fminf(x0*ca, x1*ca) + fminf(y0*sa, y1*sa) + 364.0f;
        smin[tid] = (int)floorf(mx);
    }
    __syncthreads();
    for (int i = tid; i < 60*64; i += 512) {
        int a = i >> 6, off = i & 63;
        int idx = smin[a] + off;
        srow[i] = ((unsigned)idx < 729u) ? __ldg(g_h1 + a*729 + idx) : 0.f;
    }
    __syncthreads();
    int x = bx + tx, y = by + ty;
    float xo = (float)x - 255.5f, yo = (float)y - 255.5f;
    float acc = 0.f;
    #pragma unroll 4
    for (int a = 0; a < 60; ++a) {
        float sidx = fmaf(xo, sc[a], fmaf(yo, ssn[a], 364.0f));
        float sf = floorf(sidx);
        float fr = sidx - sf;
        int local = (int)sf - smin[a];
        const float* rp = &srow[a*64 + local];
        float v0 = rp[0], v1 = rp[1];
        acc += fmaf(fr, v1 - v0, v0);
    }
    g_fbuf[5*SS + y*512 + x] = acc;
}

// ---------------- 3x3 SAME conv v4 ----------------
template<int CIN, int OCH, int TH, bool PRELU, bool ADDTO>
__global__ void __launch_bounds__(16*TH) conv3x3_v4(
    const float* __restrict__ in, float* __restrict__ out,
    const float* __restrict__ w, const float* __restrict__ bias,
    const float* __restrict__ slope, int H, int W)
{
    constexpr int CH = 4;
    constexpr int TW = 64;
    constexpr int LW = 68;
    constexpr int BS = 16*TH;
    __shared__ float sW[OCH*CIN*9];
    __shared__ float sIn[CH*(TH+2)*LW];

    int tx = threadIdx.x, ty = threadIdx.y;
    int tid = ty*16 + tx;
    int bx = blockIdx.x*TW, by = blockIdx.y*TH;
    int zo = blockIdx.z*OCH;
    size_t HW = (size_t)H*W;

    for (int i = tid; i < OCH*CIN*9; i += BS) sW[i] = __ldg(w + zo*CIN*9 + i);

    float sl = PRELU ? __ldg(slope) : 0.f;
    float acc[OCH][4];
    #pragma unroll
    for (int o = 0; o < OCH; ++o) {
        float bb = __ldg(bias + zo + o);
        #pragma unroll
        for (int p = 0; p < 4; ++p) acc[o][p] = bb;
    }

    constexpr int NCH = (CIN + CH - 1)/CH;
    #pragma unroll 1
    for (int chunk = 0; chunk < NCH; ++chunk) {
        int ic0 = chunk*CH;
        int cc = (CIN - ic0 < CH) ? (CIN - ic0) : CH;
        __syncthreads();
        int tot = cc*(TH+2)*66;
        for (int i = tid; i < tot; i += BS) {
            int c = i/((TH+2)*66);
            int rem = i - c*((TH+2)*66);
            int ly = rem/66, lx = rem - ly*66;
            int gy = by + ly - 1, gx = bx + lx - 1;
            float v = 0.f;
            if ((unsigned)gy < (unsigned)H && (unsigned)gx < (unsigned)W)
                v = __ldg(in + (size_t)(ic0 + c)*HW + (size_t)gy*W + gx);
            sIn[(c*(TH+2) + ly)*LW + lx] = v;
        }
        __syncthreads();
        #pragma unroll
        for (int c = 0; c < CH; ++c) {
            if (c >= cc) break;
            float r[3][6];
            #pragma unroll
            for (int ry = 0; ry < 3; ++ry) {
                const float* rp = &sIn[(c*(TH+2) + ty + ry)*LW + tx*4];
                float4 v4 = *reinterpret_cast<const float4*>(rp);
                r[ry][0] = v4.x; r[ry][1] = v4.y; r[ry][2] = v4.z; r[ry][3] = v4.w;
                r[ry][4] = rp[4]; r[ry][5] = rp[5];
            }
            const float* wb = &sW[(ic0 + c)*9];
            #pragma unroll
            for (int o = 0; o < OCH; ++o) {
                const float* wo = wb + o*CIN*9;
                #pragma unroll
                for (int ky = 0; ky < 3; ++ky)
                    #pragma unroll
                    for (int kx = 0; kx < 3; ++kx) {
                        float wv = wo[ky*3 + kx];
                        #pragma unroll
                        for (int p = 0; p < 4; ++p)
                            acc[o][p] = fmaf(wv, r[ky][kx+p], acc[o][p]);
                    }
            }
        }
    }

    int y = by + ty;
    int x0 = bx + tx*4;
    if (y < H) {
        bool fullvec = ((W & 3) == 0) && (x0 + 4 <= W);
        #pragma unroll
        for (int o = 0; o < OCH; ++o) {
            float* op = out + (size_t)(zo + o)*HW + (size_t)y*W;
            float v[4];
            #pragma unroll
            for (int p = 0; p < 4; ++p) {
                v[p] = acc[o][p];
                if (PRELU) v[p] = (v[p] >= 0.f) ? v[p] : sl*v[p];
            }
            if (fullvec) {
                float4* dst = reinterpret_cast<float4*>(op + x0);
                if (ADDTO) {
                    float4 e = dst[0];
                    e.x += v[0]; e.y += v[1]; e.z += v[2]; e.w += v[3];
                    dst[0] = e;
                } else {
                    dst[0] = make_float4(v[0], v[1], v[2], v[3]);
                }
            } else {
                #pragma unroll
                for (int p = 0; p < 4; ++p) {
                    int x = x0 + p;
                    if (x < W) {
                        if (ADDTO) op[x] += v[p];
                        else       op[x] = v[p];
                    }
                }
            }
        }
    }
}

// ---------------- output writer ----------------
__global__ void k_out(float* __restrict__ out, int n) {
    int i = blockIdx.x*blockDim.x + threadIdx.x;
    if (i < n) out[i] = g_fbuf[i % SS];
}

// ---------------- launch ----------------
extern "C" void kernel_launch(void* const* d_in, const int* in_sizes, int n_in,
                              void* d_out, int out_size) {
    (void)in_sizes; (void)n_in;
    const float* g     = (const float*)d_in[2];
    const float* theta = (const float*)d_in[3];
    const float* dw1 = (const float*)d_in[5];
    const float* db1 = (const float*)d_in[6];
    const float* da1 = (const float*)d_in[7];
    const float* dw2 = (const float*)d_in[8];
    const float* db2 = (const float*)d_in[9];
    const float* da2 = (const float*)d_in[10];
    const float* dw3 = (const float*)d_in[11];
    const float* db3 = (const float*)d_in[12];
    const float* pw1 = (const float*)d_in[13];
    const float* pb1 = (const float*)d_in[14];
    const float* pa1 = (const float*)d_in[15];
    const float* pw2 = (const float*)d_in[16];
    const float* pb2 = (const float*)d_in[17];
    const float* pa2 = (const float*)d_in[18];
    const float* pw3 = (const float*)d_in[19];
    const float* pb3 = (const float*)d_in[20];

    float *fbuf, *hbuf, *t1, *t2;
    cudaGetSymbolAddress((void**)&fbuf, g_fbuf);
    cudaGetSymbolAddress((void**)&hbuf, g_hbuf);
    cudaGetSymbolAddress((void**)&t1, g_t1);
    cudaGetSymbolAddress((void**)&t2, g_t2);

    k_ramp<<<6, 256>>>();
    k_init<<<512, 256>>>(g);

    // dual: OCH=4, z=8 -> 768 blocks (2x occupancy vs round 7)
    dim3 gD1(12, 8, 8), bD1(16, 8);
    dim3 gD2(12, 8, 8), bD2(16, 8);
    dim3 gD3(12, 15, 1), bD3(16, 4);
    // primal: unchanged (register-limited already)
    dim3 gP1(8, 32, 4), bP1(16, 16);
    dim3 gP2(8, 32, 4), bP2(16, 16);
    dim3 gP3(8, 64, 1), bP3(16, 8);

    for (int i = 0; i < 10; ++i) {
        // dual step
        k_radon_fwd<<<dim3(12, 60), dim3(64, 4)>>>(theta);
        conv3x3_v4<7, 4, 8, true, false><<<gD1, bD1>>>(hbuf, t1, dw1 + i*32*7*9, db1 + i*32, da1 + i, 60, 729);
        conv3x3_v4<32, 4, 8, true, false><<<gD2, bD2>>>(t1, t2, dw2 + i*32*32*9, db2 + i*32, da2 + i, 60, 729);
        conv3x3_v4<32, 5, 4, false, true><<<gD3, bD3>>>(t2, hbuf, dw3 + i*5*32*9, db3 + i*5, (const float*)0, 60, 729);
        // filter + backprojection
        k_filt<<<60, 256>>>();
        k_backproj<<<dim3(16, 32), dim3(32, 16)>>>(theta);
        // primal step
        conv3x3_v4<6, 8, 16, true, false><<<gP1, bP1>>>(fbuf, t1, pw1 + i*32*6*9, pb1 + i*32, pa1 + i, 512, 512);
        conv3x3_v4<32, 8, 16, true, false><<<gP2, bP2>>>(t1, t2, pw2 + i*32*32*9, pb2 + i*32, pa2 + i, 512, 512);
        conv3x3_v4<32, 5, 8, false, true><<<gP3, bP3>>>(t2, fbuf, pw3 + i*5*32*9, pb3 + i*5, (const float*)0, 512, 512);
    }

    k_out<<<(out_size + 255)/256, 256>>>((float*)d_out, out_size);
}

// round 9
// speedup vs baseline: 1.1121x; 1.0036x over previous
#include <cuda_runtime.h>
#include <math.h>

#define SS (512*512)
#define AD (60*729)

// ---------------- persistent device state ----------------
__device__ float g_fbuf[6*SS];    // ch0-4: f, ch5: backprojection
__device__ float g_hbuf[7*AD];    // ch0-4: h, ch5: Op_f, ch6: g (copied once)
__device__ float g_t1[32*SS];
__device__ float g_t2[32*SS];
__device__ float g_h1[AD];
__device__ float g_K2[1457];      // unwrapped ramp impulse response (scaled)

// ---------------- ramp filter impulse response ----------------
__global__ void k_ramp() {
    int o = blockIdx.x*blockDim.x + threadIdx.x;
    if (o >= 1457) return;
    int i = o - 728;
    int m = (i + 2048) & 2047;
    double kv;
    if (m == 0) {
        kv = 0.5;
    } else {
        const double PI = 3.14159265358979323846;
        double th = 2.0*PI*(double)m/2048.0;
        double c1 = cos(th), s1 = sin(th);
        double Nt = 1023.0*th;
        double cN = cos(Nt), sN = sin(Nt);
        double cN1 = cN*c1 - sN*s1, sN1 = sN*c1 + cN*s1;   // z^(N+1)
        double wr = 1.0 - 1024.0*cN + 1023.0*cN1;
        double wi =     - 1024.0*sN + 1023.0*sN1;
        double nr = c1*wr - s1*wi, ni = c1*wi + s1*wr;     // z*w
        double dr = 1.0 - c1, di = -s1;
        double d2r = dr*dr - di*di, d2i = 2.0*dr*di;       // (1-z)^2
        double dd = d2r*d2r + d2i*d2i;
        double Sre = (nr*d2r + ni*d2i)/dd;
        double f = 2.0*Sre + ((m & 1) ? -1024.0 : 1024.0);
        kv = (2.0/(2048.0*2048.0))*f;
    }
    g_K2[o] = (float)(kv * (3.14159265358979323846/120.0));
}

// ---------------- init ----------------
__global__ void k_init(const float* __restrict__ g) {
    int i = blockIdx.x*blockDim.x + threadIdx.x;
    int stride = gridDim.x*blockDim.x;
    for (int idx = i; idx < 5*SS; idx += stride) g_fbuf[idx] = 0.f;
    for (int idx = i; idx < 5*AD; idx += stride) g_hbuf[idx] = 0.f;
    for (int idx = i; idx < AD;   idx += stride) g_hbuf[6*AD+idx] = g[idx];
}

// ---------------- Radon forward: f ch1 -> g_hbuf ch5 ----------------
// with analytic valid-t-range clamping; body numerics identical to reference.
__global__ void k_radon_fwd(const float* __restrict__ theta) {
    __shared__ float red[4][64];
    int a = blockIdx.y;
    int tx = threadIdx.x, ty = threadIdx.y;
    int d = blockIdx.x*64 + tx;
    float ang = __ldg(theta + a);
    float ca = cosf(ang), sa = sinf(ang);
    const float* img = g_fbuf + SS;   // channel 1 of f
    float acc = 0.f;
    if (d < 729) {
        float s = (float)d - 364.0f;
        float bx = fmaf(s, ca, 255.5f);
        float by = fmaf(s, sa, 255.5f);
        float t_lo = -1e9f, t_hi = 1e9f;
        if (sa > 1e-6f) {
            t_lo = fmaxf(t_lo, (bx - 512.0f)/sa);
            t_hi = fminf(t_hi, (bx + 1.0f)/sa);
        } else if (bx <= -1.0f || bx >= 512.0f) {
            t_hi = -2e9f;
        }
        if (ca > 1e-6f) {
            t_lo = fmaxf(t_lo, (-1.0f - by)/ca);
            t_hi = fminf(t_hi, (512.0f - by)/ca);
        } else if (ca < -1e-6f) {
            t_lo = fmaxf(t_lo, (512.0f - by)/ca);
            t_hi = fminf(t_hi, (-1.0f - by)/ca);
        } else if (by <= -1.0f || by >= 512.0f) {
            t_hi = -2e9f;
        }
        int t0 = ty*128;
        int lo = t0, hi = t0 + 128;
        float fl = floorf(t_lo + 255.5f) - 1.0f;
        float fh = ceilf (t_hi + 255.5f) + 2.0f;
        fl = fmaxf(fl, (float)lo); fh = fminf(fh, (float)hi);
        if (fl > (float)lo) lo = (int)fl;
        if (fh < (float)hi) hi = (fh < (float)t0) ? t0 : (int)fh;
        for (int it = lo; it < hi; ++it) {
            float t = (float)it - 255.5f;
            float px = fmaf(-t, sa, bx);
            float py = fmaf( t, ca, by);
            float xf = floorf(px), yf = floorf(py);
            int xi = (int)xf, yi = (int)yf;
            float fx = px - xf, fy = py - yf;
            if ((unsigned)xi < 511u && (unsigned)yi < 511u) {
                const float* p = img + yi*512 + xi;
                float v00 = __ldg(p), v01 = __ldg(p+1);
                float v10 = __ldg(p+512), v11 = __ldg(p+513);
                float top = fmaf(fx, v01 - v00, v00);
                float bot = fmaf(fx, v11 - v10, v10);
                acc += fmaf(fy, bot - top, top);
            } else if (xi >= -1 && xi <= 511 && yi >= -1 && yi <= 511) {
                bool x0v = (xi >= 0) && (xi < 512);
                bool x1v = (xi + 1) < 512;
                bool y0v = (yi >= 0) && (yi < 512);
                bool y1v = (yi + 1) < 512;
                const float* p = img + yi*512 + xi;
                float v00 = (x0v && y0v) ? __ldg(p)     : 0.f;
                float v01 = (x1v && y0v) ? __ldg(p+1)   : 0.f;
                float v10 = (x0v && y1v) ? __ldg(p+512) : 0.f;
                float v11 = (x1v && y1v) ? __ldg(p+513) : 0.f;
                float top = fmaf(fx, v01 - v00, v00);
                float bot = fmaf(fx, v11 - v10, v10);
                acc += fmaf(fy, bot - top, top);
            }
        }
    }
    red[ty][tx] = acc;
    __syncthreads();
    if (ty == 0 && d < 729)
        g_hbuf[5*AD + a*729 + d] = red[0][tx] + red[1][tx] + red[2][tx] + red[3][tx];
}

// ---------------- fused Ram-Lak filter: h ch0 -> g_h1 ----------------
__global__ void __launch_bounds__(256) k_filt() {
    __shared__ float srow[736];
    __shared__ float sk[1536];
    int a = blockIdx.x;
    int t = threadIdx.x;
    for (int i = t; i < 729; i += 256) srow[i] = g_hbuf[a*729 + i];
    for (int i = t; i < 1536; i += 256) sk[i] = (i < 1457) ? g_K2[i] : 0.f;
    __syncthreads();
    float a0 = 0.f, a1 = 0.f, a2 = 0.f;
    #pragma unroll 4
    for (int m = 0; m < 729; ++m) {
        float r = srow[m];
        int base = 728 - m;
        a0 = fmaf(r, sk[base + t],       a0);
        a1 = fmaf(r, sk[base + t + 256], a1);
        a2 = fmaf(r, sk[base + t + 512], a2);
    }
    g_h1[a*729 + t] = a0;
    g_h1[a*729 + t + 256] = a1;
    if (t < 217) g_h1[a*729 + t + 512] = a2;
}

// ---------------- backprojection v2: smem detector windows ----------------
__global__ void __launch_bounds__(512) k_backproj(const float* __restrict__ theta) {
    __shared__ float sc[60], ssn[60];
    __shared__ int   smin[60];
    __shared__ float srow[60*64];
    int tx = threadIdx.x, ty = threadIdx.y;
    int tid = ty*32 + tx;
    int bx = blockIdx.x*32, by = blockIdx.y*16;
    float x0 = (float)bx - 255.5f, x1 = x0 + 31.0f;
    float y0 = (float)by - 255.5f, y1 = y0 + 15.0f;
    if (tid < 60) {
        float ang = __ldg(theta + tid);
        float ca = cosf(ang), sa = sinf(ang);
        sc[tid] = ca; ssn[tid] = sa;
        float mx = fminf(x0*ca, x1*ca) + fminf(y0*sa, y1*sa) + 364.0f;
        smin[tid] = (int)floorf(mx);
    }
    __syncthreads();
    for (int i = tid; i < 60*64; i += 512) {
        int a = i >> 6, off = i & 63;
        int idx = smin[a] + off;
        srow[i] = ((unsigned)idx < 729u) ? __ldg(g_h1 + a*729 + idx) : 0.f;
    }
    __syncthreads();
    int x = bx + tx, y = by + ty;
    float xo = (float)x - 255.5f, yo = (float)y - 255.5f;
    float acc = 0.f;
    #pragma unroll 4
    for (int a = 0; a < 60; ++a) {
        float sidx = fmaf(xo, sc[a], fmaf(yo, ssn[a], 364.0f));
        float sf = floorf(sidx);
        float fr = sidx - sf;
        int local = (int)sf - smin[a];
        const float* rp = &srow[a*64 + local];
        float v0 = rp[0], v1 = rp[1];
        acc += fmaf(fr, v1 - v0, v0);
    }
    g_fbuf[5*SS + y*512 + x] = acc;
}

// ---------------- 3x3 SAME conv v4 ----------------
template<int CIN, int OCH, int TH, bool PRELU, bool ADDTO>
__global__ void __launch_bounds__(16*TH) conv3x3_v4(
    const float* __restrict__ in, float* __restrict__ out,
    const float* __restrict__ w, const float* __restrict__ bias,
    const float* __restrict__ slope, int H, int W)
{
    constexpr int CH = 4;
    constexpr int TW = 64;
    constexpr int LW = 68;
    constexpr int BS = 16*TH;
    __shared__ float sW[OCH*CIN*9];
    __shared__ float sIn[CH*(TH+2)*LW];

    int tx = threadIdx.x, ty = threadIdx.y;
    int tid = ty*16 + tx;
    int bx = blockIdx.x*TW, by = blockIdx.y*TH;
    int zo = blockIdx.z*OCH;
    size_t HW = (size_t)H*W;

    for (int i = tid; i < OCH*CIN*9; i += BS) sW[i] = __ldg(w + zo*CIN*9 + i);

    float sl = PRELU ? __ldg(slope) : 0.f;
    float acc[OCH][4];
    #pragma unroll
    for (int o = 0; o < OCH; ++o) {
        float bb = __ldg(bias + zo + o);
        #pragma unroll
        for (int p = 0; p < 4; ++p) acc[o][p] = bb;
    }

    constexpr int NCH = (CIN + CH - 1)/CH;
    #pragma unroll 1
    for (int chunk = 0; chunk < NCH; ++chunk) {
        int ic0 = chunk*CH;
        int cc = (CIN - ic0 < CH) ? (CIN - ic0) : CH;
        __syncthreads();
        int tot = cc*(TH+2)*66;
        for (int i = tid; i < tot; i += BS) {
            int c = i/((TH+2)*66);
            int rem = i - c*((TH+2)*66);
            int ly = rem/66, lx = rem - ly*66;
            int gy = by + ly - 1, gx = bx + lx - 1;
            float v = 0.f;
            if ((unsigned)gy < (unsigned)H && (unsigned)gx < (unsigned)W)
                v = __ldg(in + (size_t)(ic0 + c)*HW + (size_t)gy*W + gx);
            sIn[(c*(TH+2) + ly)*LW + lx] = v;
        }
        __syncthreads();
        #pragma unroll
        for (int c = 0; c < CH; ++c) {
            if (c >= cc) break;
            float r[3][6];
            #pragma unroll
            for (int ry = 0; ry < 3; ++ry) {
                const float* rp = &sIn[(c*(TH+2) + ty + ry)*LW + tx*4];
                float4 v4 = *reinterpret_cast<const float4*>(rp);
                r[ry][0] = v4.x; r[ry][1] = v4.y; r[ry][2] = v4.z; r[ry][3] = v4.w;
                r[ry][4] = rp[4]; r[ry][5] = rp[5];
            }
            const float* wb = &sW[(ic0 + c)*9];
            #pragma unroll
            for (int o = 0; o < OCH; ++o) {
                const float* wo = wb + o*CIN*9;
                #pragma unroll
                for (int ky = 0; ky < 3; ++ky)
                    #pragma unroll
                    for (int kx = 0; kx < 3; ++kx) {
                        float wv = wo[ky*3 + kx];
                        #pragma unroll
                        for (int p = 0; p < 4; ++p)
                            acc[o][p] = fmaf(wv, r[ky][kx+p], acc[o][p]);
                    }
            }
        }
    }

    int y = by + ty;
    int x0 = bx + tx*4;
    if (y < H) {
        bool fullvec = ((W & 3) == 0) && (x0 + 4 <= W);
        #pragma unroll
        for (int o = 0; o < OCH; ++o) {
            float* op = out + (size_t)(zo + o)*HW + (size_t)y*W;
            float v[4];
            #pragma unroll
            for (int p = 0; p < 4; ++p) {
                v[p] = acc[o][p];
                if (PRELU) v[p] = (v[p] >= 0.f) ? v[p] : sl*v[p];
            }
            if (fullvec) {
                float4* dst = reinterpret_cast<float4*>(op + x0);
                if (ADDTO) {
                    float4 e = dst[0];
                    e.x += v[0]; e.y += v[1]; e.z += v[2]; e.w += v[3];
                    dst[0] = e;
                } else {
                    dst[0] = make_float4(v[0], v[1], v[2], v[3]);
                }
            } else {
                #pragma unroll
                for (int p = 0; p < 4; ++p) {
                    int x = x0 + p;
                    if (x < W) {
                        if (ADDTO) op[x] += v[p];
                        else       op[x] = v[p];
                    }
                }
            }
        }
    }
}

// ---------------- output writer ----------------
__global__ void k_out(float* __restrict__ out, int n) {
    int i = blockIdx.x*blockDim.x + threadIdx.x;
    if (i < n) out[i] = g_fbuf[i % SS];
}

// ---------------- launch ----------------
extern "C" void kernel_launch(void* const* d_in, const int* in_sizes, int n_in,
                              void* d_out, int out_size) {
    (void)in_sizes; (void)n_in;
    const float* g     = (const float*)d_in[2];
    const float* theta = (const float*)d_in[3];
    const float* dw1 = (const float*)d_in[5];
    const float* db1 = (const float*)d_in[6];
    const float* da1 = (const float*)d_in[7];
    const float* dw2 = (const float*)d_in[8];
    const float* db2 = (const float*)d_in[9];
    const float* da2 = (const float*)d_in[10];
    const float* dw3 = (const float*)d_in[11];
    const float* db3 = (const float*)d_in[12];
    const float* pw1 = (const float*)d_in[13];
    const float* pb1 = (const float*)d_in[14];
    const float* pa1 = (const float*)d_in[15];
    const float* pw2 = (const float*)d_in[16];
    const float* pb2 = (const float*)d_in[17];
    const float* pa2 = (const float*)d_in[18];
    const float* pw3 = (const float*)d_in[19];
    const float* pb3 = (const float*)d_in[20];

    float *fbuf, *hbuf, *t1, *t2;
    cudaGetSymbolAddress((void**)&fbuf, g_fbuf);
    cudaGetSymbolAddress((void**)&hbuf, g_hbuf);
    cudaGetSymbolAddress((void**)&t1, g_t1);
    cudaGetSymbolAddress((void**)&t2, g_t2);

    k_ramp<<<6, 256>>>();
    k_init<<<512, 256>>>(g);

    // dual: OCH=4, z=8 -> 768 blocks (2x occupancy vs round 7)
    dim3 gD1(12, 8, 8), bD1(16, 8);
    dim3 gD2(12, 8, 8), bD2(16, 8);
    dim3 gD3(12, 15, 1), bD3(16, 4);
    // primal: unchanged (register-limited already)
    dim3 gP1(8, 32, 4), bP1(16, 16);
    dim3 gP2(8, 32, 4), bP2(16, 16);
    dim3 gP3(8, 64, 1), bP3(16, 8);

    for (int i = 0; i < 10; ++i) {
        // dual step
        k_radon_fwd<<<dim3(12, 60), dim3(64, 4)>>>(theta);
        conv3x3_v4<7, 4, 8, true, false><<<gD1, bD1>>>(hbuf, t1, dw1 + i*32*7*9, db1 + i*32, da1 + i, 60, 729);
        conv3x3_v4<32, 4, 8, true, false><<<gD2, bD2>>>(t1, t2, dw2 + i*32*32*9, db2 + i*32, da2 + i, 60, 729);
        conv3x3_v4<32, 5, 4, false, true><<<gD3, bD3>>>(t2, hbuf, dw3 + i*5*32*9, db3 + i*5, (const float*)0, 60, 729);
        // filter + backprojection
        k_filt<<<60, 256>>>();
        k_backproj<<<dim3(16, 32), dim3(32, 16)>>>(theta);
        // primal step
        conv3x3_v4<6, 8, 16, true, false><<<gP1, bP1>>>(fbuf, t1, pw1 + i*32*6*9, pb1 + i*32, pa1 + i, 512, 512);
        conv3x3_v4<32, 8, 16, true, false><<<gP2, bP2>>>(t1, t2, pw2 + i*32*32*9, pb2 + i*32, pa2 + i, 512, 512);
        conv3x3_v4<32, 5, 8, false, true><<<gP3, bP3>>>(t2, fbuf, pw3 + i*5*32*9, pb3 + i*5, (const float*)0, 512, 512);
    }

    k_out<<<(out_size + 255)/256, 256>>>((float*)d_out, out_size);
}

// round 10
// speedup vs baseline: 1.1163x; 1.0038x over previous
#include <cuda_runtime.h>
#include <math.h>

#define SS (512*512)
#define AD (60*729)

// ---------------- persistent device state ----------------
__device__ float g_fbuf[6*SS];    // ch0-4: f, ch5: backprojection
__device__ float g_hbuf[7*AD];    // ch0-4: h, ch5: Op_f, ch6: g (copied once)
__device__ float g_t1[32*SS];
__device__ float g_t2[32*SS];
__device__ float g_h1[AD];
__device__ float g_K2[1457];      // unwrapped ramp impulse response (scaled)

// ---------------- ramp filter impulse response ----------------
__global__ void k_ramp() {
    int o = blockIdx.x*blockDim.x + threadIdx.x;
    if (o >= 1457) return;
    int i = o - 728;
    int m = (i + 2048) & 2047;
    double kv;
    if (m == 0) {
        kv = 0.5;
    } else {
        const double PI = 3.14159265358979323846;
        double th = 2.0*PI*(double)m/2048.0;
        double c1 = cos(th), s1 = sin(th);
        double Nt = 1023.0*th;
        double cN = cos(Nt), sN = sin(Nt);
        double cN1 = cN*c1 - sN*s1, sN1 = sN*c1 + cN*s1;   // z^(N+1)
        double wr = 1.0 - 1024.0*cN + 1023.0*cN1;
        double wi =     - 1024.0*sN + 1023.0*sN1;
        double nr = c1*wr - s1*wi, ni = c1*wi + s1*wr;     // z*w
        double dr = 1.0 - c1, di = -s1;
        double d2r = dr*dr - di*di, d2i = 2.0*dr*di;       // (1-z)^2
        double dd = d2r*d2r + d2i*d2i;
        double Sre = (nr*d2r + ni*d2i)/dd;
        double f = 2.0*Sre + ((m & 1) ? -1024.0 : 1024.0);
        kv = (2.0/(2048.0*2048.0))*f;
    }
    g_K2[o] = (float)(kv * (3.14159265358979323846/120.0));
}

// ---------------- init ----------------
__global__ void k_init(const float* __restrict__ g) {
    int i = blockIdx.x*blockDim.x + threadIdx.x;
    int stride = gridDim.x*blockDim.x;
    for (int idx = i; idx < 5*SS; idx += stride) g_fbuf[idx] = 0.f;
    for (int idx = i; idx < 5*AD; idx += stride) g_hbuf[idx] = 0.f;
    for (int idx = i; idx < AD;   idx += stride) g_hbuf[6*AD+idx] = g[idx];
}

// ---------------- Radon forward: f ch1 -> g_hbuf ch5 ----------------
// with analytic valid-t-range clamping; body numerics identical to reference.
__global__ void k_radon_fwd(const float* __restrict__ theta) {
    __shared__ float red[4][64];
    int a = blockIdx.y;
    int tx = threadIdx.x, ty = threadIdx.y;
    int d = blockIdx.x*64 + tx;
    float ang = __ldg(theta + a);
    float ca = cosf(ang), sa = sinf(ang);
    const float* img = g_fbuf + SS;   // channel 1 of f
    float acc = 0.f;
    if (d < 729) {
        float s = (float)d - 364.0f;
        float bx = fmaf(s, ca, 255.5f);
        float by = fmaf(s, sa, 255.5f);
        float t_lo = -1e9f, t_hi = 1e9f;
        if (sa > 1e-6f) {
            t_lo = fmaxf(t_lo, (bx - 512.0f)/sa);
            t_hi = fminf(t_hi, (bx + 1.0f)/sa);
        } else if (bx <= -1.0f || bx >= 512.0f) {
            t_hi = -2e9f;
        }
        if (ca > 1e-6f) {
            t_lo = fmaxf(t_lo, (-1.0f - by)/ca);
            t_hi = fminf(t_hi, (512.0f - by)/ca);
        } else if (ca < -1e-6f) {
            t_lo = fmaxf(t_lo, (512.0f - by)/ca);
            t_hi = fminf(t_hi, (-1.0f - by)/ca);
        } else if (by <= -1.0f || by >= 512.0f) {
            t_hi = -2e9f;
        }
        int t0 = ty*128;
        int lo = t0, hi = t0 + 128;
        float fl = floorf(t_lo + 255.5f) - 1.0f;
        float fh = ceilf (t_hi + 255.5f) + 2.0f;
        fl = fmaxf(fl, (float)lo); fh = fminf(fh, (float)hi);
        if (fl > (float)lo) lo = (int)fl;
        if (fh < (float)hi) hi = (fh < (float)t0) ? t0 : (int)fh;
        for (int it = lo; it < hi; ++it) {
            float t = (float)it - 255.5f;
            float px = fmaf(-t, sa, bx);
            float py = fmaf( t, ca, by);
            float xf = floorf(px), yf = floorf(py);
            int xi = (int)xf, yi = (int)yf;
            float fx = px - xf, fy = py - yf;
            if ((unsigned)xi < 511u && (unsigned)yi < 511u) {
                const float* p = img + yi*512 + xi;
                float v00 = __ldg(p), v01 = __ldg(p+1);
                float v10 = __ldg(p+512), v11 = __ldg(p+513);
                float top = fmaf(fx, v01 - v00, v00);
                float bot = fmaf(fx, v11 - v10, v10);
                acc += fmaf(fy, bot - top, top);
            } else if (xi >= -1 && xi <= 511 && yi >= -1 && yi <= 511) {
                bool x0v = (xi >= 0) && (xi < 512);
                bool x1v = (xi + 1) < 512;
                bool y0v = (yi >= 0) && (yi < 512);
                bool y1v = (yi + 1) < 512;
                const float* p = img + yi*512 + xi;
                float v00 = (x0v && y0v) ? __ldg(p)     : 0.f;
                float v01 = (x1v && y0v) ? __ldg(p+1)   : 0.f;
                float v10 = (x0v && y1v) ? __ldg(p+512) : 0.f;
                float v11 = (x1v && y1v) ? __ldg(p+513) : 0.f;
                float top = fmaf(fx, v01 - v00, v00);
                float bot = fmaf(fx, v11 - v10, v10);
                acc += fmaf(fy, bot - top, top);
            }
        }
    }
    red[ty][tx] = acc;
    __syncthreads();
    if (ty == 0 && d < 729)
        g_hbuf[5*AD + a*729 + d] = red[0][tx] + red[1][tx] + red[2][tx] + red[3][tx];
}

// ---------------- fused Ram-Lak filter: h ch0 -> g_h1 ----------------
__global__ void __launch_bounds__(256) k_filt() {
    __shared__ float srow[736];
    __shared__ float sk[1536];
    int a = blockIdx.x;
    int t = threadIdx.x;
    for (int i = t; i < 729; i += 256) srow[i] = g_hbuf[a*729 + i];
    for (int i = t; i < 1536; i += 256) sk[i] = (i < 1457) ? g_K2[i] : 0.f;
    __syncthreads();
    float a0 = 0.f, a1 = 0.f, a2 = 0.f;
    #pragma unroll 4
    for (int m = 0; m < 729; ++m) {
        float r = srow[m];
        int base = 728 - m;
        a0 = fmaf(r, sk[base + t],       a0);
        a1 = fmaf(r, sk[base + t + 256], a1);
        a2 = fmaf(r, sk[base + t + 512], a2);
    }
    g_h1[a*729 + t] = a0;
    g_h1[a*729 + t + 256] = a1;
    if (t < 217) g_h1[a*729 + t + 512] = a2;
}

// ---------------- backprojection v2: smem detector windows ----------------
__global__ void __launch_bounds__(512) k_backproj(const float* __restrict__ theta) {
    __shared__ float sc[60], ssn[60];
    __shared__ int   smin[60];
    __shared__ float srow[60*64];
    int tx = threadIdx.x, ty = threadIdx.y;
    int tid = ty*32 + tx;
    int bx = blockIdx.x*32, by = blockIdx.y*16;
    float x0 = (float)bx - 255.5f, x1 = x0 + 31.0f;
    float y0 = (float)by - 255.5f, y1 = y0 + 15.0f;
    if (tid < 60) {
        float ang = __ldg(theta + tid);
        float ca = cosf(ang), sa = sinf(ang);
        sc[tid] = ca; ssn[tid] = sa;
        float mx = fminf(x0*ca, x1*ca) + fminf(y0*sa, y1*sa) + 364.0f;
        smin[tid] = (int)floorf(mx);
    }
    __syncthreads();
    for (int i = tid; i < 60*64; i += 512) {
        int a = i >> 6, off = i & 63;
        int idx = smin[a] + off;
        srow[i] = ((unsigned)idx < 729u) ? __ldg(g_h1 + a*729 + idx) : 0.f;
    }
    __syncthreads();
    int x = bx + tx, y = by + ty;
    float xo = (float)x - 255.5f, yo = (float)y - 255.5f;
    float acc = 0.f;
    #pragma unroll 4
    for (int a = 0; a < 60; ++a) {
        float sidx = fmaf(xo, sc[a], fmaf(yo, ssn[a], 364.0f));
        float sf = floorf(sidx);
        float fr = sidx - sf;
        int local = (int)sf - smin[a];
        const float* rp = &srow[a*64 + local];
        float v0 = rp[0], v1 = rp[1];
        acc += fmaf(fr, v1 - v0, v0);
    }
    g_fbuf[5*SS + y*512 + x] = acc;
}

// ---------------- 3x3 SAME conv v4 ----------------
template<int CIN, int OCH, int TH, bool PRELU, bool ADDTO>
__global__ void __launch_bounds__(16*TH) conv3x3_v4(
    const float* __restrict__ in, float* __restrict__ out,
    const float* __restrict__ w, const float* __restrict__ bias,
    const float* __restrict__ slope, int H, int W)
{
    constexpr int CH = 4;
    constexpr int TW = 64;
    constexpr int LW = 68;
    constexpr int BS = 16*TH;
    __shared__ float sW[OCH*CIN*9];
    __shared__ float sIn[CH*(TH+2)*LW];

    int tx = threadIdx.x, ty = threadIdx.y;
    int tid = ty*16 + tx;
    int bx = blockIdx.x*TW, by = blockIdx.y*TH;
    int zo = blockIdx.z*OCH;
    size_t HW = (size_t)H*W;

    for (int i = tid; i < OCH*CIN*9; i += BS) sW[i] = __ldg(w + zo*CIN*9 + i);

    float sl = PRELU ? __ldg(slope) : 0.f;
    float acc[OCH][4];
    #pragma unroll
    for (int o = 0; o < OCH; ++o) {
        float bb = __ldg(bias + zo + o);
        #pragma unroll
        for (int p = 0; p < 4; ++p) acc[o][p] = bb;
    }

    constexpr int NCH = (CIN + CH - 1)/CH;
    #pragma unroll 1
    for (int chunk = 0; chunk < NCH; ++chunk) {
        int ic0 = chunk*CH;
        int cc = (CIN - ic0 < CH) ? (CIN - ic0) : CH;
        __syncthreads();
        int tot = cc*(TH+2)*66;
        for (int i = tid; i < tot; i += BS) {
            int c = i/((TH+2)*66);
            int rem = i - c*((TH+2)*66);
            int ly = rem/66, lx = rem - ly*66;
            int gy = by + ly - 1, gx = bx + lx - 1;
            float v = 0.f;
            if ((unsigned)gy < (unsigned)H && (unsigned)gx < (unsigned)W)
                v = __ldg(in + (size_t)(ic0 + c)*HW + (size_t)gy*W + gx);
            sIn[(c*(TH+2) + ly)*LW + lx] = v;
        }
        __syncthreads();
        #pragma unroll
        for (int c = 0; c < CH; ++c) {
            if (c >= cc) break;
            float r[3][6];
            #pragma unroll
            for (int ry = 0; ry < 3; ++ry) {
                const float* rp = &sIn[(c*(TH+2) + ty + ry)*LW + tx*4];
                float4 v4 = *reinterpret_cast<const float4*>(rp);
                r[ry][0] = v4.x; r[ry][1] = v4.y; r[ry][2] = v4.z; r[ry][3] = v4.w;
                r[ry][4] = rp[4]; r[ry][5] = rp[5];
            }
            const float* wb = &sW[(ic0 + c)*9];
            #pragma unroll
            for (int o = 0; o < OCH; ++o) {
                const float* wo = wb + o*CIN*9;
                #pragma unroll
                for (int ky = 0; ky < 3; ++ky)
                    #pragma unroll
                    for (int kx = 0; kx < 3; ++kx) {
                        float wv = wo[ky*3 + kx];
                        #pragma unroll
                        for (int p = 0; p < 4; ++p)
                            acc[o][p] = fmaf(wv, r[ky][kx+p], acc[o][p]);
                    }
            }
        }
    }

    int y = by + ty;
    int x0 = bx + tx*4;
    if (y < H) {
        bool fullvec = ((W & 3) == 0) && (x0 + 4 <= W);
        #pragma unroll
        for (int o = 0; o < OCH; ++o) {
            float* op = out + (size_t)(zo + o)*HW + (size_t)y*W;
            float v[4];
            #pragma unroll
            for (int p = 0; p < 4; ++p) {
                v[p] = acc[o][p];
                if (PRELU) v[p] = (v[p] >= 0.f) ? v[p] : sl*v[p];
            }
            if (fullvec) {
                float4* dst = reinterpret_cast<float4*>(op + x0);
                if (ADDTO) {
                    float4 e = dst[0];
                    e.x += v[0]; e.y += v[1]; e.z += v[2]; e.w += v[3];
                    dst[0] = e;
                } else {
                    dst[0] = make_float4(v[0], v[1], v[2], v[3]);
                }
            } else {
                #pragma unroll
                for (int p = 0; p < 4; ++p) {
                    int x = x0 + p;
                    if (x < W) {
                        if (ADDTO) op[x] += v[p];
                        else       op[x] = v[p];
                    }
                }
            }
        }
    }
}

// ---------------- output writer ----------------
__global__ void k_out(float* __restrict__ out, int n) {
    int i = blockIdx.x*blockDim.x + threadIdx.x;
    if (i < n) out[i] = g_fbuf[i % SS];
}

// ---------------- launch ----------------
extern "C" void kernel_launch(void* const* d_in, const int* in_sizes, int n_in,
                              void* d_out, int out_size) {
    (void)in_sizes; (void)n_in;
    const float* g     = (const float*)d_in[2];
    const float* theta = (const float*)d_in[3];
    const float* dw1 = (const float*)d_in[5];
    const float* db1 = (const float*)d_in[6];
    const float* da1 = (const float*)d_in[7];
    const float* dw2 = (const float*)d_in[8];
    const float* db2 = (const float*)d_in[9];
    const float* da2 = (const float*)d_in[10];
    const float* dw3 = (const float*)d_in[11];
    const float* db3 = (const float*)d_in[12];
    const float* pw1 = (const float*)d_in[13];
    const float* pb1 = (const float*)d_in[14];
    const float* pa1 = (const float*)d_in[15];
    const float* pw2 = (const float*)d_in[16];
    const float* pb2 = (const float*)d_in[17];
    const float* pa2 = (const float*)d_in[18];
    const float* pw3 = (const float*)d_in[19];
    const float* pb3 = (const float*)d_in[20];

    float *fbuf, *hbuf, *t1, *t2;
    cudaGetSymbolAddress((void**)&fbuf, g_fbuf);
    cudaGetSymbolAddress((void**)&hbuf, g_hbuf);
    cudaGetSymbolAddress((void**)&t1, g_t1);
    cudaGetSymbolAddress((void**)&t2, g_t2);

    k_ramp<<<6, 256>>>();
    k_init<<<512, 256>>>(g);

    // dual: OCH=4, z=8 -> 768 blocks (2x occupancy vs round 7)
    dim3 gD1(12, 8, 8), bD1(16, 8);
    dim3 gD2(12, 8, 8), bD2(16, 8);
    dim3 gD3(12, 15, 1), bD3(16, 4);
    // primal: unchanged (register-limited already)
    dim3 gP1(8, 32, 4), bP1(16, 16);
    dim3 gP2(8, 32, 4), bP2(16, 16);
    dim3 gP3(8, 64, 1), bP3(16, 8);

    for (int i = 0; i < 10; ++i) {
        // dual step
        k_radon_fwd<<<dim3(12, 60), dim3(64, 4)>>>(theta);
        conv3x3_v4<7, 4, 8, true, false><<<gD1, bD1>>>(hbuf, t1, dw1 + i*32*7*9, db1 + i*32, da1 + i, 60, 729);
        conv3x3_v4<32, 4, 8, true, false><<<gD2, bD2>>>(t1, t2, dw2 + i*32*32*9, db2 + i*32, da2 + i, 60, 729);
        conv3x3_v4<32, 5, 4, false, true><<<gD3, bD3>>>(t2, hbuf, dw3 + i*5*32*9, db3 + i*5, (const float*)0, 60, 729);
        // filter + backprojection
        k_filt<<<60, 256>>>();
        k_backproj<<<dim3(16, 32), dim3(32, 16)>>>(theta);
        // primal step
        conv3x3_v4<6, 8, 16, true, false><<<gP1, bP1>>>(fbuf, t1, pw1 + i*32*6*9, pb1 + i*32, pa1 + i, 512, 512);
        conv3x3_v4<32, 8, 16, true, false><<<gP2, bP2>>>(t1, t2, pw2 + i*32*32*9, pb2 + i*32, pa2 + i, 512, 512);
        conv3x3_v4<32, 5, 8, false, true><<<gP3, bP3>>>(t2, fbuf, pw3 + i*5*32*9, pb3 + i*5, (const float*)0, 512, 512);
    }

    k_out<<<(out_size + 255)/256, 256>>>((float*)d_out, out_size);
}

// round 11
// speedup vs baseline: 1.1165x; 1.0002x over previous
#include <cuda_runtime.h>
#include <math.h>

#define SS (512*512)
#define AD (60*729)

// ---------------- persistent device state ----------------
__device__ float g_fbuf[6*SS];    // ch0-4: f, ch5: backprojection
__device__ float g_hbuf[7*AD];    // ch0-4: h, ch5: Op_f, ch6: g (copied once)
__device__ float g_t1[32*SS];
__device__ float g_t2[32*SS];
__device__ float g_h1[AD];
__device__ float g_K2[1457];      // unwrapped ramp impulse response (scaled)

// ---------------- ramp filter impulse response ----------------
__global__ void k_ramp() {
    int o = blockIdx.x*blockDim.x + threadIdx.x;
    if (o >= 1457) return;
    int i = o - 728;
    int m = (i + 2048) & 2047;
    double kv;
    if (m == 0) {
        kv = 0.5;
    } else {
        const double PI = 3.14159265358979323846;
        double th = 2.0*PI*(double)m/2048.0;
        double c1 = cos(th), s1 = sin(th);
        double Nt = 1023.0*th;
        double cN = cos(Nt), sN = sin(Nt);
        double cN1 = cN*c1 - sN*s1, sN1 = sN*c1 + cN*s1;   // z^(N+1)
        double wr = 1.0 - 1024.0*cN + 1023.0*cN1;
        double wi =     - 1024.0*sN + 1023.0*sN1;
        double nr = c1*wr - s1*wi, ni = c1*wi + s1*wr;     // z*w
        double dr = 1.0 - c1, di = -s1;
        double d2r = dr*dr - di*di, d2i = 2.0*dr*di;       // (1-z)^2
        double dd = d2r*d2r + d2i*d2i;
        double Sre = (nr*d2r + ni*d2i)/dd;
        double f = 2.0*Sre + ((m & 1) ? -1024.0 : 1024.0);
        kv = (2.0/(2048.0*2048.0))*f;
    }
    g_K2[o] = (float)(kv * (3.14159265358979323846/120.0));
}

// ---------------- init ----------------
__global__ void k_init(const float* __restrict__ g) {
    int i = blockIdx.x*blockDim.x + threadIdx.x;
    int stride = gridDim.x*blockDim.x;
    for (int idx = i; idx < 5*SS; idx += stride) g_fbuf[idx] = 0.f;
    for (int idx = i; idx < 5*AD; idx += stride) g_hbuf[idx] = 0.f;
    for (int idx = i; idx < AD;   idx += stride) g_hbuf[6*AD+idx] = g[idx];
}

// ---------------- Radon forward: f ch1 -> g_hbuf ch5 ----------------
// with analytic valid-t-range clamping; body numerics identical to reference.
__global__ void k_radon_fwd(const float* __restrict__ theta) {
    __shared__ float red[4][64];
    int a = blockIdx.y;
    int tx = threadIdx.x, ty = threadIdx.y;
    int d = blockIdx.x*64 + tx;
    float ang = __ldg(theta + a);
    float ca = cosf(ang), sa = sinf(ang);
    const float* img = g_fbuf + SS;   // channel 1 of f
    float acc = 0.f;
    if (d < 729) {
        float s = (float)d - 364.0f;
        float bx = fmaf(s, ca, 255.5f);
        float by = fmaf(s, sa, 255.5f);
        float t_lo = -1e9f, t_hi = 1e9f;
        if (sa > 1e-6f) {
            t_lo = fmaxf(t_lo, (bx - 512.0f)/sa);
            t_hi = fminf(t_hi, (bx + 1.0f)/sa);
        } else if (bx <= -1.0f || bx >= 512.0f) {
            t_hi = -2e9f;
        }
        if (ca > 1e-6f) {
            t_lo = fmaxf(t_lo, (-1.0f - by)/ca);
            t_hi = fminf(t_hi, (512.0f - by)/ca);
        } else if (ca < -1e-6f) {
            t_lo = fmaxf(t_lo, (512.0f - by)/ca);
            t_hi = fminf(t_hi, (-1.0f - by)/ca);
        } else if (by <= -1.0f || by >= 512.0f) {
            t_hi = -2e9f;
        }
        int t0 = ty*128;
        int lo = t0, hi = t0 + 128;
        float fl = floorf(t_lo + 255.5f) - 1.0f;
        float fh = ceilf (t_hi + 255.5f) + 2.0f;
        fl = fmaxf(fl, (float)lo); fh = fminf(fh, (float)hi);
        if (fl > (float)lo) lo = (int)fl;
        if (fh < (float)hi) hi = (fh < (float)t0) ? t0 : (int)fh;
        for (int it = lo; it < hi; ++it) {
            float t = (float)it - 255.5f;
            float px = fmaf(-t, sa, bx);
            float py = fmaf( t, ca, by);
            float xf = floorf(px), yf = floorf(py);
            int xi = (int)xf, yi = (int)yf;
            float fx = px - xf, fy = py - yf;
            if ((unsigned)xi < 511u && (unsigned)yi < 511u) {
                const float* p = img + yi*512 + xi;
                float v00 = __ldg(p), v01 = __ldg(p+1);
                float v10 = __ldg(p+512), v11 = __ldg(p+513);
                float top = fmaf(fx, v01 - v00, v00);
                float bot = fmaf(fx, v11 - v10, v10);
                acc += fmaf(fy, bot - top, top);
            } else if (xi >= -1 && xi <= 511 && yi >= -1 && yi <= 511) {
                bool x0v = (xi >= 0) && (xi < 512);
                bool x1v = (xi + 1) < 512;
                bool y0v = (yi >= 0) && (yi < 512);
                bool y1v = (yi + 1) < 512;
                const float* p = img + yi*512 + xi;
                float v00 = (x0v && y0v) ? __ldg(p)     : 0.f;
                float v01 = (x1v && y0v) ? __ldg(p+1)   : 0.f;
                float v10 = (x0v && y1v) ? __ldg(p+512) : 0.f;
                float v11 = (x1v && y1v) ? __ldg(p+513) : 0.f;
                float top = fmaf(fx, v01 - v00, v00);
                float bot = fmaf(fx, v11 - v10, v10);
                acc += fmaf(fy, bot - top, top);
            }
        }
    }
    red[ty][tx] = acc;
    __syncthreads();
    if (ty == 0 && d < 729)
        g_hbuf[5*AD + a*729 + d] = red[0][tx] + red[1][tx] + red[2][tx] + red[3][tx];
}

// ---------------- fused Ram-Lak filter: h ch0 -> g_h1 ----------------
__global__ void __launch_bounds__(256) k_filt() {
    __shared__ float srow[736];
    __shared__ float sk[1536];
    int a = blockIdx.x;
    int t = threadIdx.x;
    for (int i = t; i < 729; i += 256) srow[i] = g_hbuf[a*729 + i];
    for (int i = t; i < 1536; i += 256) sk[i] = (i < 1457) ? g_K2[i] : 0.f;
    __syncthreads();
    float a0 = 0.f, a1 = 0.f, a2 = 0.f;
    #pragma unroll 4
    for (int m = 0; m < 729; ++m) {
        float r = srow[m];
        int base = 728 - m;
        a0 = fmaf(r, sk[base + t],       a0);
        a1 = fmaf(r, sk[base + t + 256], a1);
        a2 = fmaf(r, sk[base + t + 512], a2);
    }
    g_h1[a*729 + t] = a0;
    g_h1[a*729 + t + 256] = a1;
    if (t < 217) g_h1[a*729 + t + 512] = a2;
}

// ---------------- backprojection v2: smem detector windows ----------------
__global__ void __launch_bounds__(512) k_backproj(const float* __restrict__ theta) {
    __shared__ float sc[60], ssn[60];
    __shared__ int   smin[60];
    __shared__ float srow[60*64];
    int tx = threadIdx.x, ty = threadIdx.y;
    int tid = ty*32 + tx;
    int bx = blockIdx.x*32, by = blockIdx.y*16;
    float x0 = (float)bx - 255.5f, x1 = x0 + 31.0f;
    float y0 = (float)by - 255.5f, y1 = y0 + 15.0f;
    if (tid < 60) {
        float ang = __ldg(theta + tid);
        float ca = cosf(ang), sa = sinf(ang);
        sc[tid] = ca; ssn[tid] = sa;
        float mx = fminf(x0*ca, x1*ca) + fminf(y0*sa, y1*sa) + 364.0f;
        smin[tid] = (int)floorf(mx);
    }
    __syncthreads();
    for (int i = tid; i < 60*64; i += 512) {
        int a = i >> 6, off = i & 63;
        int idx = smin[a] + off;
        srow[i] = ((unsigned)idx < 729u) ? __ldg(g_h1 + a*729 + idx) : 0.f;
    }
    __syncthreads();
    int x = bx + tx, y = by + ty;
    float xo = (float)x - 255.5f, yo = (float)y - 255.5f;
    float acc = 0.f;
    #pragma unroll 4
    for (int a = 0; a < 60; ++a) {
        float sidx = fmaf(xo, sc[a], fmaf(yo, ssn[a], 364.0f));
        float sf = floorf(sidx);
        float fr = sidx - sf;
        int local = (int)sf - smin[a];
        const float* rp = &srow[a*64 + local];
        float v0 = rp[0], v1 = rp[1];
        acc += fmaf(fr, v1 - v0, v0);
    }
    g_fbuf[5*SS + y*512 + x] = acc;
}

// ---------------- 3x3 SAME conv v4 ----------------
template<int CIN, int OCH, int TH, bool PRELU, bool ADDTO>
__global__ void __launch_bounds__(16*TH) conv3x3_v4(
    const float* __restrict__ in, float* __restrict__ out,
    const float* __restrict__ w, const float* __restrict__ bias,
    const float* __restrict__ slope, int H, int W)
{
    constexpr int CH = 4;
    constexpr int TW = 64;
    constexpr int LW = 68;
    constexpr int BS = 16*TH;
    __shared__ float sW[OCH*CIN*9];
    __shared__ float sIn[CH*(TH+2)*LW];

    int tx = threadIdx.x, ty = threadIdx.y;
    int tid = ty*16 + tx;
    int bx = blockIdx.x*TW, by = blockIdx.y*TH;
    int zo = blockIdx.z*OCH;
    size_t HW = (size_t)H*W;

    for (int i = tid; i < OCH*CIN*9; i += BS) sW[i] = __ldg(w + zo*CIN*9 + i);

    float sl = PRELU ? __ldg(slope) : 0.f;
    float acc[OCH][4];
    #pragma unroll
    for (int o = 0; o < OCH; ++o) {
        float bb = __ldg(bias + zo + o);
        #pragma unroll
        for (int p = 0; p < 4; ++p) acc[o][p] = bb;
    }

    constexpr int NCH = (CIN + CH - 1)/CH;
    #pragma unroll 1
    for (int chunk = 0; chunk < NCH; ++chunk) {
        int ic0 = chunk*CH;
        int cc = (CIN - ic0 < CH) ? (CIN - ic0) : CH;
        __syncthreads();
        int tot = cc*(TH+2)*66;
        for (int i = tid; i < tot; i += BS) {
            int c = i/((TH+2)*66);
            int rem = i - c*((TH+2)*66);
            int ly = rem/66, lx = rem - ly*66;
            int gy = by + ly - 1, gx = bx + lx - 1;
            float v = 0.f;
            if ((unsigned)gy < (unsigned)H && (unsigned)gx < (unsigned)W)
                v = __ldg(in + (size_t)(ic0 + c)*HW + (size_t)gy*W + gx);
            sIn[(c*(TH+2) + ly)*LW + lx] = v;
        }
        __syncthreads();
        #pragma unroll
        for (int c = 0; c < CH; ++c) {
            if (c >= cc) break;
            float r[3][6];
            #pragma unroll
            for (int ry = 0; ry < 3; ++ry) {
                const float* rp = &sIn[(c*(TH+2) + ty + ry)*LW + tx*4];
                float4 v4 = *reinterpret_cast<const float4*>(rp);
                r[ry][0] = v4.x; r[ry][1] = v4.y; r[ry][2] = v4.z; r[ry][3] = v4.w;
                r[ry][4] = rp[4]; r[ry][5] = rp[5];
            }
            const float* wb = &sW[(ic0 + c)*9];
            #pragma unroll
            for (int o = 0; o < OCH; ++o) {
                const float* wo = wb + o*CIN*9;
                #pragma unroll
                for (int ky = 0; ky < 3; ++ky)
                    #pragma unroll
                    for (int kx = 0; kx < 3; ++kx) {
                        float wv = wo[ky*3 + kx];
                        #pragma unroll
                        for (int p = 0; p < 4; ++p)
                            acc[o][p] = fmaf(wv, r[ky][kx+p], acc[o][p]);
                    }
            }
        }
    }

    int y = by + ty;
    int x0 = bx + tx*4;
    if (y < H) {
        bool fullvec = ((W & 3) == 0) && (x0 + 4 <= W);
        #pragma unroll
        for (int o = 0; o < OCH; ++o) {
            float* op = out + (size_t)(zo + o)*HW + (size_t)y*W;
            float v[4];
            #pragma unroll
            for (int p = 0; p < 4; ++p) {
                v[p] = acc[o][p];
                if (PRELU) v[p] = (v[p] >= 0.f) ? v[p] : sl*v[p];
            }
            if (fullvec) {
                float4* dst = reinterpret_cast<float4*>(op + x0);
                if (ADDTO) {
                    float4 e = dst[0];
                    e.x += v[0]; e.y += v[1]; e.z += v[2]; e.w += v[3];
                    dst[0] = e;
                } else {
                    dst[0] = make_float4(v[0], v[1], v[2], v[3]);
                }
            } else {
                #pragma unroll
                for (int p = 0; p < 4; ++p) {
                    int x = x0 + p;
                    if (x < W) {
                        if (ADDTO) op[x] += v[p];
                        else       op[x] = v[p];
                    }
                }
            }
        }
    }
}

// ---------------- output writer ----------------
__global__ void k_out(float* __restrict__ out, int n) {
    int i = blockIdx.x*blockDim.x + threadIdx.x;
    if (i < n) out[i] = g_fbuf[i % SS];
}

// ---------------- launch ----------------
extern "C" void kernel_launch(void* const* d_in, const int* in_sizes, int n_in,
                              void* d_out, int out_size) {
    (void)in_sizes; (void)n_in;
    const float* g     = (const float*)d_in[2];
    const float* theta = (const float*)d_in[3];
    const float* dw1 = (const float*)d_in[5];
    const float* db1 = (const float*)d_in[6];
    const float* da1 = (const float*)d_in[7];
    const float* dw2 = (const float*)d_in[8];
    const float* db2 = (const float*)d_in[9];
    const float* da2 = (const float*)d_in[10];
    const float* dw3 = (const float*)d_in[11];
    const float* db3 = (const float*)d_in[12];
    const float* pw1 = (const float*)d_in[13];
    const float* pb1 = (const float*)d_in[14];
    const float* pa1 = (const float*)d_in[15];
    const float* pw2 = (const float*)d_in[16];
    const float* pb2 = (const float*)d_in[17];
    const float* pa2 = (const float*)d_in[18];
    const float* pw3 = (const float*)d_in[19];
    const float* pb3 = (const float*)d_in[20];

    float *fbuf, *hbuf, *t1, *t2;
    cudaGetSymbolAddress((void**)&fbuf, g_fbuf);
    cudaGetSymbolAddress((void**)&hbuf, g_hbuf);
    cudaGetSymbolAddress((void**)&t1, g_t1);
    cudaGetSymbolAddress((void**)&t2, g_t2);

    k_ramp<<<6, 256>>>();
    k_init<<<512, 256>>>(g);

    // dual: OCH=4, z=8 -> 768 blocks (2x occupancy vs round 7)
    dim3 gD1(12, 8, 8), bD1(16, 8);
    dim3 gD2(12, 8, 8), bD2(16, 8);
    dim3 gD3(12, 15, 1), bD3(16, 4);
    // primal: unchanged (register-limited already)
    dim3 gP1(8, 32, 4), bP1(16, 16);
    dim3 gP2(8, 32, 4), bP2(16, 16);
    dim3 gP3(8, 64, 1), bP3(16, 8);

    for (int i = 0; i < 10; ++i) {
        // dual step
        k_radon_fwd<<<dim3(12, 60), dim3(64, 4)>>>(theta);
        conv3x3_v4<7, 4, 8, true, false><<<gD1, bD1>>>(hbuf, t1, dw1 + i*32*7*9, db1 + i*32, da1 + i, 60, 729);
        conv3x3_v4<32, 4, 8, true, false><<<gD2, bD2>>>(t1, t2, dw2 + i*32*32*9, db2 + i*32, da2 + i, 60, 729);
        conv3x3_v4<32, 5, 4, false, true><<<gD3, bD3>>>(t2, hbuf, dw3 + i*5*32*9, db3 + i*5, (const float*)0, 60, 729);
        // filter + backprojection
        k_filt<<<60, 256>>>();
        k_backproj<<<dim3(16, 32), dim3(32, 16)>>>(theta);
        // primal step
        conv3x3_v4<6, 8, 16, true, false><<<gP1, bP1>>>(fbuf, t1, pw1 + i*32*6*9, pb1 + i*32, pa1 + i, 512, 512);
        conv3x3_v4<32, 8, 16, true, false><<<gP2, bP2>>>(t1, t2, pw2 + i*32*32*9, pb2 + i*32, pa2 + i, 512, 512);
        conv3x3_v4<32, 5, 8, false, true><<<gP3, bP3>>>(t2, fbuf, pw3 + i*5*32*9, pb3 + i*5, (const float*)0, 512, 512);
    }

    k_out<<<(out_size + 255)/256, 256>>>((float*)d_out, out_size);
}